// round 1
// baseline (speedup 1.0000x reference)
#include <cuda_runtime.h>
#include <math.h>

#define BATCH   2
#define SEQ     2048
#define HIDDEN  1024
#define NHEADS  16
#define HEADD   64
#define MROWS   (BATCH*SEQ)      // 4096
#define QKVDIM  (3*HIDDEN)       // 3072
#define ATT_SCALE 0.125f         // 1/sqrt(64)
#define LNEPS   1e-5f

// ---------------- scratch (static device memory; no runtime allocation) ---
__device__ float g_x[(size_t)MROWS * HIDDEN];        // 16 MB  normalized input
__device__ float g_qkv[(size_t)MROWS * QKVDIM];      // 48 MB  qkv (rope in place)
__device__ float g_attn[(size_t)MROWS * HIDDEN];     // 16 MB  attn out pre-proj
__device__ float g_probs_fb[(size_t)BATCH * NHEADS * SEQ * SEQ]; // 512 MB fallback

// ---------------- LayerNorm -----------------------------------------------
__global__ void ln_kernel(const float* __restrict__ hs,
                          const float* __restrict__ gamma,
                          const float* __restrict__ beta) {
    int row = blockIdx.x;
    const float* x = hs + (size_t)row * HIDDEN;
    __shared__ float red[256];
    int t = threadIdx.x;

    float s = 0.f;
    for (int i = t; i < HIDDEN; i += 256) s += x[i];
    red[t] = s; __syncthreads();
    for (int st = 128; st > 0; st >>= 1) { if (t < st) red[t] += red[t + st]; __syncthreads(); }
    float mean = red[0] * (1.0f / HIDDEN);
    __syncthreads();

    float v = 0.f;
    for (int i = t; i < HIDDEN; i += 256) { float d = x[i] - mean; v += d * d; }
    red[t] = v; __syncthreads();
    for (int st = 128; st > 0; st >>= 1) { if (t < st) red[t] += red[t + st]; __syncthreads(); }
    float var = red[0] * (1.0f / HIDDEN);
    float inv = rsqrtf(var + LNEPS);

    float* out = g_x + (size_t)row * HIDDEN;
    for (int i = t; i < HIDDEN; i += 256)
        out[i] = (x[i] - mean) * inv * gamma[i] + beta[i];
}

// ---------------- generic C[M,N] = A[M,K] * B[N,K]^T (both K-contiguous) --
// 64x64 tile, BK=16, 256 threads, 4x4 per thread.
__global__ void gemm_nt(const float* __restrict__ A, const float* __restrict__ B,
                        float* __restrict__ C, int M, int N, int K) {
    __shared__ float As[16][65];   // [k][m]
    __shared__ float Bs[16][65];   // [k][n]
    int m0 = blockIdx.y * 64, n0 = blockIdx.x * 64;
    int tid = threadIdx.x;
    int tx = tid & 15, ty = tid >> 4;

    float acc[4][4] = {};
    for (int k0 = 0; k0 < K; k0 += 16) {
        #pragma unroll
        for (int r = 0; r < 4; r++) {
            int idx = tid + r * 256;
            int mm = idx >> 4, kk = idx & 15;
            As[kk][mm] = A[(size_t)(m0 + mm) * K + k0 + kk];
            Bs[kk][mm] = B[(size_t)(n0 + mm) * K + k0 + kk];
        }
        __syncthreads();
        #pragma unroll
        for (int kk = 0; kk < 16; kk++) {
            float a[4], b[4];
            #pragma unroll
            for (int i = 0; i < 4; i++) { a[i] = As[kk][ty * 4 + i]; b[i] = Bs[kk][tx * 4 + i]; }
            #pragma unroll
            for (int i = 0; i < 4; i++)
                #pragma unroll
                for (int j = 0; j < 4; j++)
                    acc[i][j] += a[i] * b[j];
        }
        __syncthreads();
    }
    #pragma unroll
    for (int i = 0; i < 4; i++)
        #pragma unroll
        for (int j = 0; j < 4; j++)
            C[(size_t)(m0 + ty * 4 + i) * N + n0 + tx * 4 + j] = acc[i][j];
}

// ---------------- RoPE (interleaved, reference-exact formula) -------------
// new[2j]   = x[2j]*c_j   - x[32+j]*s_j
// new[2j+1] = x[2j+1]*c_j + x[j]*s_j
__global__ void rope_kernel() {
    int t = blockIdx.x * blockDim.x + threadIdx.x;
    if (t >= MROWS * NHEADS) return;
    int r = t >> 4;          // global row (b*SEQ + s)
    int h = t & 15;
    int pos = r & (SEQ - 1); // s
    const float LOG_TH = 9.210340371976184f; // ln(10000)

    float c[32], s[32];
    #pragma unroll
    for (int j = 0; j < 32; j++) {
        float freq = __expf(-(float)j * (LOG_TH / 32.0f));
        float ang = (float)pos * freq;
        sincosf(ang, &s[j], &c[j]);
    }

    float* base = g_qkv + (size_t)r * QKVDIM + h * HEADD;
    #pragma unroll
    for (int part = 0; part < 2; part++) {   // q then k
        float* x = base + part * HIDDEN;
        float old[64];
        #pragma unroll
        for (int i = 0; i < 64; i++) old[i] = x[i];
        #pragma unroll
        for (int j = 0; j < 32; j++) {
            x[2 * j]     = old[2 * j]     * c[j] - old[32 + j] * s[j];
            x[2 * j + 1] = old[2 * j + 1] * c[j] + old[j]      * s[j];
        }
    }
}

// ---------------- scores = scale * Q K^T (causal tiles only) --------------
__global__ void scores_kernel(float* __restrict__ probs) {
    int bh = blockIdx.z;
    int mt = blockIdx.y, nt = blockIdx.x;
    if (nt > mt) return;                 // fully masked tile
    int b = bh >> 4, h = bh & 15;
    int m0 = mt * 64, n0 = nt * 64;

    __shared__ float Qs[64][65];   // [k][m]
    __shared__ float Ks[64][65];   // [k][n]
    int tid = threadIdx.x;
    int tx = tid & 15, ty = tid >> 4;

    #pragma unroll
    for (int r = 0; r < 16; r++) {
        int idx = tid + r * 256;
        int k = idx & 63, m = idx >> 6;
        Qs[k][m] = g_qkv[(size_t)(b * SEQ + m0 + m) * QKVDIM + h * HEADD + k];
        Ks[k][m] = g_qkv[(size_t)(b * SEQ + n0 + m) * QKVDIM + HIDDEN + h * HEADD + k];
    }
    __syncthreads();

    float acc[4][4] = {};
    #pragma unroll
    for (int kk = 0; kk < 64; kk++) {
        float a[4], bb[4];
        #pragma unroll
        for (int i = 0; i < 4; i++) { a[i] = Qs[kk][ty * 4 + i]; bb[i] = Ks[kk][tx * 4 + i]; }
        #pragma unroll
        for (int i = 0; i < 4; i++)
            #pragma unroll
            for (int j = 0; j < 4; j++)
                acc[i][j] += a[i] * bb[j];
    }

    #pragma unroll
    for (int i = 0; i < 4; i++) {
        int row = m0 + ty * 4 + i;
        #pragma unroll
        for (int j = 0; j < 4; j++) {
            int col = n0 + tx * 4 + j;
            if (col <= row)
                probs[((size_t)bh * SEQ + row) * SEQ + col] = acc[i][j] * ATT_SCALE;
        }
    }
}

// ---------------- row softmax (in place) + zero-fill masked tail ----------
__global__ void softmax_kernel(float* __restrict__ probs) {
    int bh = blockIdx.y;
    int row = blockIdx.x;
    float* p = probs + ((size_t)bh * SEQ + row) * SEQ;
    int len = row + 1;
    int t = threadIdx.x;

    __shared__ float buf[SEQ];
    __shared__ float red[256];

    float mx = -3.4e38f;
    for (int i = t; i < len; i += 256) { float v = p[i]; buf[i] = v; mx = fmaxf(mx, v); }
    red[t] = mx; __syncthreads();
    for (int st = 128; st > 0; st >>= 1) { if (t < st) red[t] = fmaxf(red[t], red[t + st]); __syncthreads(); }
    mx = red[0]; __syncthreads();

    float sum = 0.f;
    for (int i = t; i < len; i += 256) { float e = expf(buf[i] - mx); buf[i] = e; sum += e; }
    red[t] = sum; __syncthreads();
    for (int st = 128; st > 0; st >>= 1) { if (t < st) red[t] += red[t + st]; __syncthreads(); }
    float inv = 1.0f / red[0];

    for (int i = t; i < len; i += 256) p[i] = buf[i] * inv;
    for (int i = len + t; i < SEQ; i += 256) p[i] = 0.f;
}

// ---------------- out_attn = probs @ V (causal k-tiles only) --------------
__global__ void pv_kernel(const float* __restrict__ probs) {
    int bh = blockIdx.y;
    int mt = blockIdx.x;
    int b = bh >> 4, h = bh & 15;
    int m0 = mt * 64;

    __shared__ float Ps[64][65];   // [k][m]
    __shared__ float Vs[64][65];   // [k][n]
    int tid = threadIdx.x;
    int tx = tid & 15, ty = tid >> 4;

    float acc[4][4] = {};
    for (int kt = 0; kt <= mt; kt++) {
        int k0 = kt * 64;
        #pragma unroll
        for (int r = 0; r < 16; r++) {
            int idx = tid + r * 256;
            int kk = idx & 63, mm = idx >> 6;
            Ps[kk][mm] = probs[((size_t)bh * SEQ + m0 + mm) * SEQ + k0 + kk];
            // V row is (b*SEQ + k0 + mm), contiguous over head dim (kk here = n)
            Vs[mm][kk] = g_qkv[(size_t)(b * SEQ + k0 + mm) * QKVDIM + 2 * HIDDEN + h * HEADD + kk];
        }
        __syncthreads();
        #pragma unroll
        for (int kk = 0; kk < 64; kk++) {
            float a[4], v[4];
            #pragma unroll
            for (int i = 0; i < 4; i++) { a[i] = Ps[kk][ty * 4 + i]; v[i] = Vs[kk][tx * 4 + i]; }
            #pragma unroll
            for (int i = 0; i < 4; i++)
                #pragma unroll
                for (int j = 0; j < 4; j++)
                    acc[i][j] += a[i] * v[j];
        }
        __syncthreads();
    }

    #pragma unroll
    for (int i = 0; i < 4; i++)
        #pragma unroll
        for (int j = 0; j < 4; j++)
            g_attn[(size_t)(b * SEQ + m0 + ty * 4 + i) * HIDDEN + h * HEADD + tx * 4 + j] = acc[i][j];
}

// ---------------------------------------------------------------------------
extern "C" void kernel_launch(void* const* d_in, const int* in_sizes, int n_in,
                              void* d_out, int out_size) {
    const float* hs    = (const float*)d_in[0];
    const float* Wqkv  = (const float*)d_in[1];
    const float* Wout  = (const float*)d_in[2];
    const float* gamma = (const float*)d_in[3];
    const float* beta  = (const float*)d_in[4];
    // d_in[5]: attention_mask (causal, hardcoded)

    float* out = (float*)d_out;
    const size_t OUT_ELEMS   = (size_t)MROWS * HIDDEN;
    const size_t PROBS_ELEMS = (size_t)BATCH * NHEADS * SEQ * SEQ;

    float* probs;
    if ((size_t)out_size >= OUT_ELEMS + PROBS_ELEMS) {
        probs = out + OUT_ELEMS;
    } else {
        void* p; cudaGetSymbolAddress(&p, g_probs_fb);
        probs = (float*)p;
    }

    void* px; cudaGetSymbolAddress(&px, g_x);
    void* pq; cudaGetSymbolAddress(&pq, g_qkv);
    void* pa; cudaGetSymbolAddress(&pa, g_attn);
    float* xn   = (float*)px;
    float* qkv  = (float*)pq;
    float* attn = (float*)pa;

    // 1. LayerNorm
    ln_kernel<<<MROWS, 256>>>(hs, gamma, beta);

    // 2. QKV projection: [4096,1024] x [3072,1024]^T -> [4096,3072]
    gemm_nt<<<dim3(QKVDIM / 64, MROWS / 64), 256>>>(xn, Wqkv, qkv, MROWS, QKVDIM, HIDDEN);

    // 3. RoPE on q,k in place
    rope_kernel<<<(MROWS * NHEADS + 127) / 128, 128>>>();

    // 4. scores (causal tiles only)
    scores_kernel<<<dim3(SEQ / 64, SEQ / 64, BATCH * NHEADS), 256>>>(probs);

    // 5. softmax rows + zero masked tail
    softmax_kernel<<<dim3(SEQ, BATCH * NHEADS), 256>>>(probs);

    // 6. probs @ V
    pv_kernel<<<dim3(SEQ / 64, BATCH * NHEADS), 256>>>(probs);

    // 7. output projection: [4096,1024] x [1024,1024]^T
    gemm_nt<<<dim3(HIDDEN / 64, MROWS / 64), 256>>>(attn, Wout, out, MROWS, HIDDEN, HIDDEN);
}

// round 2
// speedup vs baseline: 1.5863x; 1.5863x over previous
#include <cuda_runtime.h>
#include <math.h>

#define BATCH   2
#define SEQ     2048
#define HIDDEN  1024
#define NHEADS  16
#define HEADD   64
#define MROWS   (BATCH*SEQ)      // 4096
#define QKVDIM  (3*HIDDEN)       // 3072
#define ATT_SCALE 0.125f
#define LNEPS   1e-5f

// ---------------- scratch (static device memory) ---------------------------
__device__ float g_x[(size_t)MROWS * HIDDEN];
__device__ float g_qkv[(size_t)MROWS * QKVDIM];
__device__ float g_attn[(size_t)MROWS * HIDDEN];
__device__ float g_probs_fb[(size_t)BATCH * NHEADS * SEQ * SEQ];

// ---------------- LayerNorm (single pass, float4, shuffle) -----------------
__global__ void ln_kernel(const float* __restrict__ hs,
                          const float* __restrict__ gamma,
                          const float* __restrict__ beta) {
    int row = blockIdx.x;
    int t = threadIdx.x;
    const float4* x4 = (const float4*)(hs + (size_t)row * HIDDEN);
    float4 v = x4[t];                                   // 256 threads x 4 = 1024
    float s  = v.x + v.y + v.z + v.w;
    float sq = v.x*v.x + v.y*v.y + v.z*v.z + v.w*v.w;
    #pragma unroll
    for (int o = 16; o > 0; o >>= 1) {
        s  += __shfl_xor_sync(0xffffffffu, s,  o);
        sq += __shfl_xor_sync(0xffffffffu, sq, o);
    }
    __shared__ float ss[8], ssq[8];
    if ((t & 31) == 0) { ss[t >> 5] = s; ssq[t >> 5] = sq; }
    __syncthreads();
    float tot = 0.f, totq = 0.f;
    #pragma unroll
    for (int i = 0; i < 8; i++) { tot += ss[i]; totq += ssq[i]; }
    float mean = tot * (1.0f / HIDDEN);
    float var  = totq * (1.0f / HIDDEN) - mean * mean;
    float inv  = rsqrtf(var + LNEPS);

    float4 g = ((const float4*)gamma)[t];
    float4 b = ((const float4*)beta)[t];
    float4 o;
    o.x = (v.x - mean) * inv * g.x + b.x;
    o.y = (v.y - mean) * inv * g.y + b.y;
    o.z = (v.z - mean) * inv * g.z + b.z;
    o.w = (v.w - mean) * inv * g.w + b.w;
    ((float4*)(g_x + (size_t)row * HIDDEN))[t] = o;
}

// ---------------- 128x128 SGEMM: C[M,N] = A[M,K] * B[N,K]^T ----------------
// BK=16, 256 threads, 8x8/thread, register-staged double buffer.
__global__ void __launch_bounds__(256) gemm128(const float* __restrict__ A,
                                               const float* __restrict__ B,
                                               float* __restrict__ C,
                                               int M, int N, int K) {
    __shared__ float As[2][16][132];
    __shared__ float Bs[2][16][132];
    int m0 = blockIdx.y * 128, n0 = blockIdx.x * 128;
    int tid = threadIdx.x;
    int lrow = tid >> 1;
    int lk   = (tid & 1) * 8;
    const float* Ap = A + (size_t)(m0 + lrow) * K + lk;
    const float* Bp = B + (size_t)(n0 + lrow) * K + lk;
    int tx = tid & 15, ty = tid >> 4;

    float acc[8][8] = {};
    float4 ra0, ra1, rb0, rb1;

    ra0 = *(const float4*)(Ap);     ra1 = *(const float4*)(Ap + 4);
    rb0 = *(const float4*)(Bp);     rb1 = *(const float4*)(Bp + 4);
    #pragma unroll
    for (int q = 0; q < 4; q++) {
        As[0][lk + q][lrow]     = ((float*)&ra0)[q];
        As[0][lk + 4 + q][lrow] = ((float*)&ra1)[q];
        Bs[0][lk + q][lrow]     = ((float*)&rb0)[q];
        Bs[0][lk + 4 + q][lrow] = ((float*)&rb1)[q];
    }
    __syncthreads();

    int T = K >> 4;
    for (int kt = 0; kt < T; kt++) {
        int cur = kt & 1;
        if (kt + 1 < T) {
            const float* Ap2 = Ap + (kt + 1) * 16;
            const float* Bp2 = Bp + (kt + 1) * 16;
            ra0 = *(const float4*)(Ap2);  ra1 = *(const float4*)(Ap2 + 4);
            rb0 = *(const float4*)(Bp2);  rb1 = *(const float4*)(Bp2 + 4);
        }
        #pragma unroll
        for (int kk = 0; kk < 16; kk++) {
            float4 a0 = *(const float4*)&As[cur][kk][ty * 4];
            float4 a1 = *(const float4*)&As[cur][kk][ty * 4 + 64];
            float4 b0 = *(const float4*)&Bs[cur][kk][tx * 4];
            float4 b1 = *(const float4*)&Bs[cur][kk][tx * 4 + 64];
            float av[8] = {a0.x,a0.y,a0.z,a0.w,a1.x,a1.y,a1.z,a1.w};
            float bv[8] = {b0.x,b0.y,b0.z,b0.w,b1.x,b1.y,b1.z,b1.w};
            #pragma unroll
            for (int i = 0; i < 8; i++)
                #pragma unroll
                for (int j = 0; j < 8; j++)
                    acc[i][j] += av[i] * bv[j];
        }
        if (kt + 1 < T) {
            int nxt = cur ^ 1;
            #pragma unroll
            for (int q = 0; q < 4; q++) {
                As[nxt][lk + q][lrow]     = ((float*)&ra0)[q];
                As[nxt][lk + 4 + q][lrow] = ((float*)&ra1)[q];
                Bs[nxt][lk + q][lrow]     = ((float*)&rb0)[q];
                Bs[nxt][lk + 4 + q][lrow] = ((float*)&rb1)[q];
            }
            __syncthreads();
        }
    }

    #pragma unroll
    for (int ih = 0; ih < 2; ih++)
        #pragma unroll
        for (int i = 0; i < 4; i++) {
            int rm = m0 + ty * 4 + ih * 64 + i;
            float* Crow = C + (size_t)rm * N + n0;
            float4 w0 = {acc[ih*4+i][0], acc[ih*4+i][1], acc[ih*4+i][2], acc[ih*4+i][3]};
            float4 w1 = {acc[ih*4+i][4], acc[ih*4+i][5], acc[ih*4+i][6], acc[ih*4+i][7]};
            *(float4*)(Crow + tx * 4)      = w0;
            *(float4*)(Crow + tx * 4 + 64) = w1;
        }
}

// ---------------- RoPE (interleaved) ---------------------------------------
__global__ void rope_kernel() {
    int t = blockIdx.x * blockDim.x + threadIdx.x;
    if (t >= MROWS * NHEADS) return;
    int r = t >> 4;
    int h = t & 15;
    int pos = r & (SEQ - 1);
    const float LOG_TH = 9.210340371976184f;

    float c[32], s[32];
    #pragma unroll
    for (int j = 0; j < 32; j++) {
        float freq = __expf(-(float)j * (LOG_TH / 32.0f));
        float ang = (float)pos * freq;
        sincosf(ang, &s[j], &c[j]);
    }

    float* base = g_qkv + (size_t)r * QKVDIM + h * HEADD;
    #pragma unroll
    for (int part = 0; part < 2; part++) {
        float* x = base + part * HIDDEN;
        float old[64];
        #pragma unroll
        for (int i = 0; i < 64; i++) old[i] = x[i];
        #pragma unroll
        for (int j = 0; j < 32; j++) {
            x[2 * j]     = old[2 * j]     * c[j] - old[32 + j] * s[j];
            x[2 * j + 1] = old[2 * j + 1] * c[j] + old[j]      * s[j];
        }
    }
}

// ---------------- scores: 128x128 tiles, causal, zero-fills masked tiles ---
__global__ void __launch_bounds__(256) scores_kernel(float* __restrict__ probs) {
    int nt = blockIdx.x;
    int mt = 15 - blockIdx.y;            // heavy row-tiles scheduled first
    int bh = blockIdx.z;
    int b = bh >> 4, h = bh & 15;
    int m0 = mt * 128, n0 = nt * 128;
    int tid = threadIdx.x;
    int tx = tid & 15, ty = tid >> 4;

    if (nt > mt) {
        // fully masked tile: write zeros (float4), 128x128 per block
        float4 z = {0.f, 0.f, 0.f, 0.f};
        #pragma unroll
        for (int ih = 0; ih < 2; ih++)
            #pragma unroll
            for (int i = 0; i < 4; i++) {
                int rm = m0 + ty * 4 + ih * 64 + i;
                float* row = probs + ((size_t)bh * SEQ + rm) * SEQ + n0;
                *(float4*)(row + tx * 4)      = z;
                *(float4*)(row + tx * 4 + 64) = z;
            }
        return;
    }

    __shared__ float Qs[16][132];
    __shared__ float Ks[16][132];
    int lrow = tid >> 1;
    int lk   = (tid & 1) * 8;
    const float* Qp = g_qkv + (size_t)(b * SEQ + m0 + lrow) * QKVDIM + h * HEADD + lk;
    const float* Kp = g_qkv + (size_t)(b * SEQ + n0 + lrow) * QKVDIM + HIDDEN + h * HEADD + lk;

    float acc[8][8] = {};
    for (int kt = 0; kt < 4; kt++) {
        float4 q0 = *(const float4*)(Qp + kt * 16);
        float4 q1 = *(const float4*)(Qp + kt * 16 + 4);
        float4 k0 = *(const float4*)(Kp + kt * 16);
        float4 k1 = *(const float4*)(Kp + kt * 16 + 4);
        #pragma unroll
        for (int q = 0; q < 4; q++) {
            Qs[lk + q][lrow]     = ((float*)&q0)[q];
            Qs[lk + 4 + q][lrow] = ((float*)&q1)[q];
            Ks[lk + q][lrow]     = ((float*)&k0)[q];
            Ks[lk + 4 + q][lrow] = ((float*)&k1)[q];
        }
        __syncthreads();
        #pragma unroll
        for (int kk = 0; kk < 16; kk++) {
            float4 a0 = *(const float4*)&Qs[kk][ty * 4];
            float4 a1 = *(const float4*)&Qs[kk][ty * 4 + 64];
            float4 b0 = *(const float4*)&Ks[kk][tx * 4];
            float4 b1 = *(const float4*)&Ks[kk][tx * 4 + 64];
            float av[8] = {a0.x,a0.y,a0.z,a0.w,a1.x,a1.y,a1.z,a1.w};
            float bv[8] = {b0.x,b0.y,b0.z,b0.w,b1.x,b1.y,b1.z,b1.w};
            #pragma unroll
            for (int i = 0; i < 8; i++)
                #pragma unroll
                for (int j = 0; j < 8; j++)
                    acc[i][j] += av[i] * bv[j];
        }
        __syncthreads();
    }

    if (nt < mt) {
        #pragma unroll
        for (int ih = 0; ih < 2; ih++)
            #pragma unroll
            for (int i = 0; i < 4; i++) {
                int rm = m0 + ty * 4 + ih * 64 + i;
                float* row = probs + ((size_t)bh * SEQ + rm) * SEQ + n0;
                float4 w0 = {acc[ih*4+i][0]*ATT_SCALE, acc[ih*4+i][1]*ATT_SCALE,
                             acc[ih*4+i][2]*ATT_SCALE, acc[ih*4+i][3]*ATT_SCALE};
                float4 w1 = {acc[ih*4+i][4]*ATT_SCALE, acc[ih*4+i][5]*ATT_SCALE,
                             acc[ih*4+i][6]*ATT_SCALE, acc[ih*4+i][7]*ATT_SCALE};
                *(float4*)(row + tx * 4)      = w0;
                *(float4*)(row + tx * 4 + 64) = w1;
            }
    } else {
        // diagonal tile: scalar writes, zero above diagonal
        #pragma unroll
        for (int ih = 0; ih < 2; ih++)
            #pragma unroll
            for (int i = 0; i < 4; i++) {
                int rm = m0 + ty * 4 + ih * 64 + i;
                float* row = probs + ((size_t)bh * SEQ + rm) * SEQ;
                #pragma unroll
                for (int jh = 0; jh < 2; jh++)
                    #pragma unroll
                    for (int j = 0; j < 4; j++) {
                        int cn = n0 + tx * 4 + jh * 64 + j;
                        row[cn] = (cn <= rm) ? acc[ih*4+i][jh*4+j] * ATT_SCALE : 0.f;
                    }
            }
    }
}

// ---------------- row softmax over [0, row] (masked tail already zero) -----
__global__ void softmax_kernel(float* __restrict__ probs) {
    int bh = blockIdx.y;
    int row = blockIdx.x;
    float* p = probs + ((size_t)bh * SEQ + row) * SEQ;
    int len = row + 1;
    int t = threadIdx.x;

    __shared__ float buf[SEQ];
    __shared__ float red[8];

    float mx = -3.4e38f;
    int n4 = len >> 2;
    const float4* p4 = (const float4*)p;
    float4* b4 = (float4*)buf;
    for (int i = t; i < n4; i += 256) {
        float4 v = p4[i]; b4[i] = v;
        mx = fmaxf(mx, fmaxf(fmaxf(v.x, v.y), fmaxf(v.z, v.w)));
    }
    for (int i = (n4 << 2) + t; i < len; i += 256) { float v = p[i]; buf[i] = v; mx = fmaxf(mx, v); }
    #pragma unroll
    for (int o = 16; o > 0; o >>= 1) mx = fmaxf(mx, __shfl_xor_sync(0xffffffffu, mx, o));
    if ((t & 31) == 0) red[t >> 5] = mx;
    __syncthreads();
    mx = red[0];
    #pragma unroll
    for (int i = 1; i < 8; i++) mx = fmaxf(mx, red[i]);
    __syncthreads();

    float sum = 0.f;
    for (int i = t; i < len; i += 256) { float e = __expf(buf[i] - mx); buf[i] = e; sum += e; }
    #pragma unroll
    for (int o = 16; o > 0; o >>= 1) sum += __shfl_xor_sync(0xffffffffu, sum, o);
    if ((t & 31) == 0) red[t >> 5] = sum;
    __syncthreads();
    float tot = 0.f;
    #pragma unroll
    for (int i = 0; i < 8; i++) tot += red[i];
    float inv = 1.0f / tot;

    float4* o4 = (float4*)p;
    for (int i = t; i < n4; i += 256) {
        float4 v = b4[i];
        v.x *= inv; v.y *= inv; v.z *= inv; v.w *= inv;
        o4[i] = v;
    }
    for (int i = (n4 << 2) + t; i < len; i += 256) p[i] = buf[i] * inv;
}

// ---------------- PV: 128x64 tiles, BK=32, reads zero-filled rectangle -----
__global__ void __launch_bounds__(256) pv_kernel(const float* __restrict__ probs) {
    int bh = blockIdx.y;
    int mt = (int)gridDim.x - 1 - (int)blockIdx.x;   // heavy tiles first
    int b = bh >> 4, h = bh & 15;
    int m0 = mt * 128;

    __shared__ float Ps[32][132];
    __shared__ float Vs[32][68];
    int tid = threadIdx.x;
    int tx = tid & 15, ty = tid >> 4;

    int prow = tid >> 1;
    int pk   = (tid & 1) * 16;
    int vk = tid >> 3;
    int vc = (tid & 7) * 8;

    const float* Prow = probs + ((size_t)bh * SEQ + m0 + prow) * SEQ;
    const float* Vbase = g_qkv + (size_t)(b * SEQ) * QKVDIM + 2 * HIDDEN + h * HEADD;

    float acc[8][4] = {};
    int ktmax = (mt + 1) * 4;
    for (int kt = 0; kt < ktmax; kt++) {
        int k0 = kt * 32;
        #pragma unroll
        for (int q4 = 0; q4 < 4; q4++) {
            float4 v = *(const float4*)(Prow + k0 + pk + q4 * 4);
            Ps[pk + q4 * 4 + 0][prow] = v.x;
            Ps[pk + q4 * 4 + 1][prow] = v.y;
            Ps[pk + q4 * 4 + 2][prow] = v.z;
            Ps[pk + q4 * 4 + 3][prow] = v.w;
        }
        {
            const float* vr = Vbase + (size_t)(k0 + vk) * QKVDIM + vc;
            *(float4*)&Vs[vk][vc]     = *(const float4*)(vr);
            *(float4*)&Vs[vk][vc + 4] = *(const float4*)(vr + 4);
        }
        __syncthreads();
        #pragma unroll
        for (int kk = 0; kk < 32; kk++) {
            float4 a0 = *(const float4*)&Ps[kk][ty * 4];
            float4 a1 = *(const float4*)&Ps[kk][ty * 4 + 64];
            float4 bb = *(const float4*)&Vs[kk][tx * 4];
            float av[8] = {a0.x,a0.y,a0.z,a0.w,a1.x,a1.y,a1.z,a1.w};
            float bv[4] = {bb.x,bb.y,bb.z,bb.w};
            #pragma unroll
            for (int i = 0; i < 8; i++)
                #pragma unroll
                for (int j = 0; j < 4; j++)
                    acc[i][j] += av[i] * bv[j];
        }
        __syncthreads();
    }

    #pragma unroll
    for (int ih = 0; ih < 2; ih++)
        #pragma unroll
        for (int i = 0; i < 4; i++) {
            int rm = m0 + ty * 4 + ih * 64 + i;
            float4 w = {acc[ih*4+i][0], acc[ih*4+i][1], acc[ih*4+i][2], acc[ih*4+i][3]};
            *(float4*)(g_attn + (size_t)(b * SEQ + rm) * HIDDEN + h * HEADD + tx * 4) = w;
        }
}

// ---------------------------------------------------------------------------
extern "C" void kernel_launch(void* const* d_in, const int* in_sizes, int n_in,
                              void* d_out, int out_size) {
    const float* hs    = (const float*)d_in[0];
    const float* Wqkv  = (const float*)d_in[1];
    const float* Wout  = (const float*)d_in[2];
    const float* gamma = (const float*)d_in[3];
    const float* beta  = (const float*)d_in[4];

    float* out = (float*)d_out;
    const size_t OUT_ELEMS   = (size_t)MROWS * HIDDEN;
    const size_t PROBS_ELEMS = (size_t)BATCH * NHEADS * SEQ * SEQ;

    float* probs;
    if ((size_t)out_size >= OUT_ELEMS + PROBS_ELEMS) {
        probs = out + OUT_ELEMS;
    } else {
        void* p; cudaGetSymbolAddress(&p, g_probs_fb);
        probs = (float*)p;
    }

    void* px; cudaGetSymbolAddress(&px, g_x);
    void* pq; cudaGetSymbolAddress(&pq, g_qkv);
    void* pa; cudaGetSymbolAddress(&pa, g_attn);
    float* xn   = (float*)px;
    float* qkv  = (float*)pq;
    float* attn = (float*)pa;

    // 1. LayerNorm
    ln_kernel<<<MROWS, 256>>>(hs, gamma, beta);

    // 2. QKV projection: [4096,1024] x [3072,1024]^T
    gemm128<<<dim3(QKVDIM / 128, MROWS / 128), 256>>>(xn, Wqkv, qkv, MROWS, QKVDIM, HIDDEN);

    // 3. RoPE in place
    rope_kernel<<<(MROWS * NHEADS + 127) / 128, 128>>>();

    // 4. scores (writes zeros in masked region too)
    scores_kernel<<<dim3(SEQ / 128, SEQ / 128, BATCH * NHEADS), 256>>>(probs);

    // 5. softmax rows
    softmax_kernel<<<dim3(SEQ, BATCH * NHEADS), 256>>>(probs);

    // 6. probs @ V
    pv_kernel<<<dim3(SEQ / 128, BATCH * NHEADS), 256>>>(probs);

    // 7. output projection
    gemm128<<<dim3(HIDDEN / 128, MROWS / 128), 256>>>(attn, Wout, out, MROWS, HIDDEN, HIDDEN);
}

// round 4
// speedup vs baseline: 1.9203x; 1.2105x over previous
#include <cuda_runtime.h>
#include <cuda_bf16.h>
#include <cstdint>
#include <math.h>

#define BATCH   2
#define SEQ     2048
#define HIDDEN  1024
#define NHEADS  16
#define HEADD   64
#define MROWS   (BATCH*SEQ)      // 4096
#define QKVDIM  (3*HIDDEN)       // 3072
#define KSPLIT  3072             // K' = 3*1024 (hi,hi,lo x hi,lo,hi)
#define ATT_SCALE 0.125f
#define LNEPS   1e-5f

// ---------------- scratch (static device memory) ---------------------------
__device__ __nv_bfloat16 g_a2[(size_t)MROWS * KSPLIT];     // 24 MB  LN out split
__device__ __nv_bfloat16 g_wqkv2[(size_t)QKVDIM * KSPLIT]; // 18 MB
__device__ __nv_bfloat16 g_wout2[(size_t)HIDDEN * KSPLIT]; // 6 MB
__device__ __nv_bfloat16 g_attn2[(size_t)MROWS * KSPLIT];  // 24 MB  attn split
__device__ float g_qkv[(size_t)MROWS * QKVDIM];            // 48 MB
__device__ float g_probs_fb[(size_t)BATCH * NHEADS * SEQ * SEQ];

__device__ __forceinline__ uint32_t smem_u32(const void* p) {
    uint32_t a;
    asm("{ .reg .u64 t; cvta.to.shared.u64 t, %1; cvt.u32.u64 %0, t; }" : "=r"(a) : "l"(p));
    return a;
}

// ---------------- bf16 split helpers ----------------------------------------
__device__ __forceinline__ unsigned short bfb(float v) {
    __nv_bfloat16 h = __float2bfloat16(v);
    return *(unsigned short*)&h;
}
__device__ __forceinline__ float bf2f(unsigned short u) {
    __nv_bfloat16 h = *(__nv_bfloat16*)&u;
    return __bfloat162float(h);
}
// write 4 consecutive values as (hi,hi,lo) triple-split at row base (stride KSPLIT)
__device__ __forceinline__ void store_split4(__nv_bfloat16* rowbase, int k,
                                             float v0, float v1, float v2, float v3) {
    unsigned short h0 = bfb(v0), h1 = bfb(v1), h2 = bfb(v2), h3 = bfb(v3);
    unsigned short l0 = bfb(v0 - bf2f(h0)), l1 = bfb(v1 - bf2f(h1));
    unsigned short l2 = bfb(v2 - bf2f(h2)), l3 = bfb(v3 - bf2f(h3));
    uint2 hw = { (uint32_t)h0 | ((uint32_t)h1 << 16), (uint32_t)h2 | ((uint32_t)h3 << 16) };
    uint2 lw = { (uint32_t)l0 | ((uint32_t)l1 << 16), (uint32_t)l2 | ((uint32_t)l3 << 16) };
    *(uint2*)(rowbase + k)        = hw;
    *(uint2*)(rowbase + 1024 + k) = hw;
    *(uint2*)(rowbase + 2048 + k) = lw;
}

// ---------------- LayerNorm -> split bf16 -----------------------------------
__global__ void ln_kernel(const float* __restrict__ hs,
                          const float* __restrict__ gamma,
                          const float* __restrict__ beta) {
    int row = blockIdx.x;
    int t = threadIdx.x;
    const float4* x4 = (const float4*)(hs + (size_t)row * HIDDEN);
    float4 v = x4[t];
    float s  = v.x + v.y + v.z + v.w;
    float sq = v.x*v.x + v.y*v.y + v.z*v.z + v.w*v.w;
    #pragma unroll
    for (int o = 16; o > 0; o >>= 1) {
        s  += __shfl_xor_sync(0xffffffffu, s,  o);
        sq += __shfl_xor_sync(0xffffffffu, sq, o);
    }
    __shared__ float ss[8], ssq[8];
    if ((t & 31) == 0) { ss[t >> 5] = s; ssq[t >> 5] = sq; }
    __syncthreads();
    float tot = 0.f, totq = 0.f;
    #pragma unroll
    for (int i = 0; i < 8; i++) { tot += ss[i]; totq += ssq[i]; }
    float mean = tot * (1.0f / HIDDEN);
    float var  = totq * (1.0f / HIDDEN) - mean * mean;
    float inv  = rsqrtf(var + LNEPS);

    float4 g = ((const float4*)gamma)[t];
    float4 b = ((const float4*)beta)[t];
    float o0 = (v.x - mean) * inv * g.x + b.x;
    float o1 = (v.y - mean) * inv * g.y + b.y;
    float o2 = (v.z - mean) * inv * g.z + b.z;
    float o3 = (v.w - mean) * inv * g.w + b.w;
    store_split4(g_a2 + (size_t)row * KSPLIT, t * 4, o0, o1, o2, o3);
}

// ---------------- weight conversion: W[N][1024] f32 -> (hi,lo,hi) split -----
__global__ void conv_w(const float* __restrict__ W, __nv_bfloat16* __restrict__ W2, int total) {
    int gid = blockIdx.x * blockDim.x + threadIdx.x;
    int i4 = gid * 4;
    if (i4 >= total) return;
    int n = i4 >> 10, k = i4 & 1023;
    float4 w = *(const float4*)(W + i4);
    unsigned short h0 = bfb(w.x), h1 = bfb(w.y), h2 = bfb(w.z), h3 = bfb(w.w);
    unsigned short l0 = bfb(w.x - bf2f(h0)), l1 = bfb(w.y - bf2f(h1));
    unsigned short l2 = bfb(w.z - bf2f(h2)), l3 = bfb(w.w - bf2f(h3));
    uint2 hw = { (uint32_t)h0 | ((uint32_t)h1 << 16), (uint32_t)h2 | ((uint32_t)h3 << 16) };
    uint2 lw = { (uint32_t)l0 | ((uint32_t)l1 << 16), (uint32_t)l2 | ((uint32_t)l3 << 16) };
    __nv_bfloat16* rb = W2 + (size_t)n * KSPLIT;
    *(uint2*)(rb + k)        = hw;   // B region 0: hi
    *(uint2*)(rb + 1024 + k) = lw;   // B region 1: lo
    *(uint2*)(rb + 2048 + k) = hw;   // B region 2: hi
}

// ---------------- mma.sync bf16 GEMM: C[M,N] = A2 . B2^T, K'=3072 ----------
// CTA tile 128x128, 8 warps (4x2), warp tile 32x64, m16n8k16 atoms.
// A in smem [m][k], B in smem [n][k], k-contiguous, row stride 40 bf16 (pad 8).
#define SROW 40
#define KCHUNK 32
#define NCHUNK (KSPLIT / KCHUNK)   // 96

__device__ __forceinline__ void ldmat4(uint32_t& r0, uint32_t& r1,
                                       uint32_t& r2, uint32_t& r3, uint32_t addr) {
    asm volatile("ldmatrix.sync.aligned.m8n8.x4.shared.b16 {%0,%1,%2,%3}, [%4];"
                 : "=r"(r0), "=r"(r1), "=r"(r2), "=r"(r3) : "r"(addr));
}
__device__ __forceinline__ void mma16816(float* c, const uint32_t* a, uint32_t b0, uint32_t b1) {
    asm volatile("mma.sync.aligned.m16n8k16.row.col.f32.bf16.bf16.f32 "
                 "{%0,%1,%2,%3}, {%4,%5,%6,%7}, {%8,%9}, {%0,%1,%2,%3};"
                 : "+f"(c[0]), "+f"(c[1]), "+f"(c[2]), "+f"(c[3])
                 : "r"(a[0]), "r"(a[1]), "r"(a[2]), "r"(a[3]), "r"(b0), "r"(b1));
}

__global__ void __launch_bounds__(256) gemm_bf16(const __nv_bfloat16* __restrict__ A2,
                                                 const __nv_bfloat16* __restrict__ B2,
                                                 float* __restrict__ C, int ldc) {
    __shared__ __nv_bfloat16 As[2][128 * SROW];
    __shared__ __nv_bfloat16 Bs[2][128 * SROW];

    int tid = threadIdx.x, lane = tid & 31, w = tid >> 5;
    int wm = w >> 1, wn = w & 1;
    int m0 = blockIdx.y * 128, n0 = blockIdx.x * 128;

    int grow = tid >> 1;
    int gseg = (tid & 1) * 16;             // bf16 element offset within chunk
    const __nv_bfloat16* Ag = A2 + (size_t)(m0 + grow) * KSPLIT + gseg;
    const __nv_bfloat16* Bg = B2 + (size_t)(n0 + grow) * KSPLIT + gseg;

    float acc[2][8][4] = {};

    // ldmatrix base addresses (lane-mapped): row_off = lane&15, k_off = (lane>>4)*8
    uint32_t aB = smem_u32(&As[0][0]) + (uint32_t)(((wm * 32 + (lane & 15)) * SROW + (lane >> 4) * 8) * 2);
    uint32_t bB = smem_u32(&Bs[0][0]) + (uint32_t)(((wn * 64 + (lane & 15)) * SROW + (lane >> 4) * 8) * 2);
    const uint32_t BUFOFF = 128 * SROW * 2;

    // prologue: load chunk 0 into buffer 0
    {
        uint4 a0 = *(const uint4*)(Ag);
        uint4 a1 = *(const uint4*)(Ag + 8);
        uint4 b0 = *(const uint4*)(Bg);
        uint4 b1 = *(const uint4*)(Bg + 8);
        *(uint4*)&As[0][grow * SROW + gseg]     = a0;
        *(uint4*)&As[0][grow * SROW + gseg + 8] = a1;
        *(uint4*)&Bs[0][grow * SROW + gseg]     = b0;
        *(uint4*)&Bs[0][grow * SROW + gseg + 8] = b1;
    }
    __syncthreads();

    for (int kc = 0; kc < NCHUNK; kc++) {
        int cur = kc & 1;
        uint4 pa0, pa1, pb0, pb1;
        if (kc + 1 < NCHUNK) {
            const __nv_bfloat16* Ap = Ag + (kc + 1) * KCHUNK;
            const __nv_bfloat16* Bp = Bg + (kc + 1) * KCHUNK;
            pa0 = *(const uint4*)(Ap);
            pa1 = *(const uint4*)(Ap + 8);
            pb0 = *(const uint4*)(Bp);
            pb1 = *(const uint4*)(Bp + 8);
        }

        uint32_t abase = aB + cur * BUFOFF;
        uint32_t bbase = bB + cur * BUFOFF;
        #pragma unroll
        for (int ks = 0; ks < 2; ks++) {             // two k16 steps per chunk
            uint32_t koff = ks * 16 * 2;             // bytes
            uint32_t af[2][4];
            ldmat4(af[0][0], af[0][1], af[0][2], af[0][3], abase + koff);
            ldmat4(af[1][0], af[1][1], af[1][2], af[1][3], abase + 16 * SROW * 2 + koff);
            uint32_t bf_[4][4];
            #pragma unroll
            for (int n2 = 0; n2 < 4; n2++)
                ldmat4(bf_[n2][0], bf_[n2][1], bf_[n2][2], bf_[n2][3],
                       bbase + n2 * 16 * SROW * 2 + koff);
            #pragma unroll
            for (int mi = 0; mi < 2; mi++)
                #pragma unroll
                for (int ni = 0; ni < 8; ni++) {
                    int n2 = ni >> 1, p = ni & 1;
                    mma16816(acc[mi][ni], af[mi], bf_[n2][p], bf_[n2][p + 2]);
                }
        }

        if (kc + 1 < NCHUNK) {
            int nxt = cur ^ 1;
            *(uint4*)&As[nxt][grow * SROW + gseg]     = pa0;
            *(uint4*)&As[nxt][grow * SROW + gseg + 8] = pa1;
            *(uint4*)&Bs[nxt][grow * SROW + gseg]     = pb0;
            *(uint4*)&Bs[nxt][grow * SROW + gseg + 8] = pb1;
            __syncthreads();
        }
    }

    // epilogue: c0,c1 -> (row, col..col+1); c2,c3 -> (row+8, col..col+1)
    #pragma unroll
    for (int mi = 0; mi < 2; mi++)
        #pragma unroll
        for (int ni = 0; ni < 8; ni++) {
            int row = m0 + wm * 32 + mi * 16 + (lane >> 2);
            int col = n0 + wn * 64 + ni * 8 + (lane & 3) * 2;
            float2 w0 = { acc[mi][ni][0], acc[mi][ni][1] };
            float2 w1 = { acc[mi][ni][2], acc[mi][ni][3] };
            *(float2*)(C + (size_t)row * ldc + col)       = w0;
            *(float2*)(C + (size_t)(row + 8) * ldc + col) = w1;
        }
}

// ---------------- RoPE (interleaved) ---------------------------------------
__global__ void rope_kernel() {
    int t = blockIdx.x * blockDim.x + threadIdx.x;
    if (t >= MROWS * NHEADS) return;
    int r = t >> 4;
    int h = t & 15;
    int pos = r & (SEQ - 1);
    const float LOG_TH = 9.210340371976184f;

    float c[32], s[32];
    #pragma unroll
    for (int j = 0; j < 32; j++) {
        float freq = __expf(-(float)j * (LOG_TH / 32.0f));
        float ang = (float)pos * freq;
        sincosf(ang, &s[j], &c[j]);
    }

    float* base = g_qkv + (size_t)r * QKVDIM + h * HEADD;
    #pragma unroll
    for (int part = 0; part < 2; part++) {
        float* x = base + part * HIDDEN;
        float old[64];
        #pragma unroll
        for (int i = 0; i < 64; i++) old[i] = x[i];
        #pragma unroll
        for (int j = 0; j < 32; j++) {
            x[2 * j]     = old[2 * j]     * c[j] - old[32 + j] * s[j];
            x[2 * j + 1] = old[2 * j + 1] * c[j] + old[j]      * s[j];
        }
    }
}

// ---------------- scores: 128x128 tiles, causal -----------------------------
__global__ void __launch_bounds__(256) scores_kernel(float* __restrict__ probs) {
    int nt = blockIdx.x;
    int mt = 15 - blockIdx.y;
    int bh = blockIdx.z;
    int b = bh >> 4, h = bh & 15;
    int m0 = mt * 128, n0 = nt * 128;
    int tid = threadIdx.x;
    int tx = tid & 15, ty = tid >> 4;

    if (nt > mt) {
        float4 z = {0.f, 0.f, 0.f, 0.f};
        #pragma unroll
        for (int ih = 0; ih < 2; ih++)
            #pragma unroll
            for (int i = 0; i < 4; i++) {
                int rm = m0 + ty * 4 + ih * 64 + i;
                float* row = probs + ((size_t)bh * SEQ + rm) * SEQ + n0;
                *(float4*)(row + tx * 4)      = z;
                *(float4*)(row + tx * 4 + 64) = z;
            }
        return;
    }

    __shared__ float Qs[16][132];
    __shared__ float Ks[16][132];
    int lrow = tid >> 1;
    int lk   = (tid & 1) * 8;
    const float* Qp = g_qkv + (size_t)(b * SEQ + m0 + lrow) * QKVDIM + h * HEADD + lk;
    const float* Kp = g_qkv + (size_t)(b * SEQ + n0 + lrow) * QKVDIM + HIDDEN + h * HEADD + lk;

    float acc[8][8] = {};
    for (int kt = 0; kt < 4; kt++) {
        float4 q0 = *(const float4*)(Qp + kt * 16);
        float4 q1 = *(const float4*)(Qp + kt * 16 + 4);
        float4 k0 = *(const float4*)(Kp + kt * 16);
        float4 k1 = *(const float4*)(Kp + kt * 16 + 4);
        #pragma unroll
        for (int q = 0; q < 4; q++) {
            Qs[lk + q][lrow]     = ((float*)&q0)[q];
            Qs[lk + 4 + q][lrow] = ((float*)&q1)[q];
            Ks[lk + q][lrow]     = ((float*)&k0)[q];
            Ks[lk + 4 + q][lrow] = ((float*)&k1)[q];
        }
        __syncthreads();
        #pragma unroll
        for (int kk = 0; kk < 16; kk++) {
            float4 a0 = *(const float4*)&Qs[kk][ty * 4];
            float4 a1 = *(const float4*)&Qs[kk][ty * 4 + 64];
            float4 b0 = *(const float4*)&Ks[kk][tx * 4];
            float4 b1 = *(const float4*)&Ks[kk][tx * 4 + 64];
            float av[8] = {a0.x,a0.y,a0.z,a0.w,a1.x,a1.y,a1.z,a1.w};
            float bv[8] = {b0.x,b0.y,b0.z,b0.w,b1.x,b1.y,b1.z,b1.w};
            #pragma unroll
            for (int i = 0; i < 8; i++)
                #pragma unroll
                for (int j = 0; j < 8; j++)
                    acc[i][j] += av[i] * bv[j];
        }
        __syncthreads();
    }

    if (nt < mt) {
        #pragma unroll
        for (int ih = 0; ih < 2; ih++)
            #pragma unroll
            for (int i = 0; i < 4; i++) {
                int rm = m0 + ty * 4 + ih * 64 + i;
                float* row = probs + ((size_t)bh * SEQ + rm) * SEQ + n0;
                float4 w0 = {acc[ih*4+i][0]*ATT_SCALE, acc[ih*4+i][1]*ATT_SCALE,
                             acc[ih*4+i][2]*ATT_SCALE, acc[ih*4+i][3]*ATT_SCALE};
                float4 w1 = {acc[ih*4+i][4]*ATT_SCALE, acc[ih*4+i][5]*ATT_SCALE,
                             acc[ih*4+i][6]*ATT_SCALE, acc[ih*4+i][7]*ATT_SCALE};
                *(float4*)(row + tx * 4)      = w0;
                *(float4*)(row + tx * 4 + 64) = w1;
            }
    } else {
        #pragma unroll
        for (int ih = 0; ih < 2; ih++)
            #pragma unroll
            for (int i = 0; i < 4; i++) {
                int rm = m0 + ty * 4 + ih * 64 + i;
                float* row = probs + ((size_t)bh * SEQ + rm) * SEQ;
                #pragma unroll
                for (int jh = 0; jh < 2; jh++)
                    #pragma unroll
                    for (int j = 0; j < 4; j++) {
                        int cn = n0 + tx * 4 + jh * 64 + j;
                        row[cn] = (cn <= rm) ? acc[ih*4+i][jh*4+j] * ATT_SCALE : 0.f;
                    }
            }
    }
}

// ---------------- row softmax ------------------------------------------------
__global__ void softmax_kernel(float* __restrict__ probs) {
    int bh = blockIdx.y;
    int row = blockIdx.x;
    float* p = probs + ((size_t)bh * SEQ + row) * SEQ;
    int len = row + 1;
    int t = threadIdx.x;

    __shared__ float buf[SEQ];
    __shared__ float red[8];

    float mx = -3.4e38f;
    int n4 = len >> 2;
    const float4* p4 = (const float4*)p;
    float4* b4 = (float4*)buf;
    for (int i = t; i < n4; i += 256) {
        float4 v = p4[i]; b4[i] = v;
        mx = fmaxf(mx, fmaxf(fmaxf(v.x, v.y), fmaxf(v.z, v.w)));
    }
    for (int i = (n4 << 2) + t; i < len; i += 256) { float v = p[i]; buf[i] = v; mx = fmaxf(mx, v); }
    #pragma unroll
    for (int o = 16; o > 0; o >>= 1) mx = fmaxf(mx, __shfl_xor_sync(0xffffffffu, mx, o));
    if ((t & 31) == 0) red[t >> 5] = mx;
    __syncthreads();
    mx = red[0];
    #pragma unroll
    for (int i = 1; i < 8; i++) mx = fmaxf(mx, red[i]);
    __syncthreads();

    float sum = 0.f;
    for (int i = t; i < len; i += 256) { float e = __expf(buf[i] - mx); buf[i] = e; sum += e; }
    #pragma unroll
    for (int o = 16; o > 0; o >>= 1) sum += __shfl_xor_sync(0xffffffffu, sum, o);
    if ((t & 31) == 0) red[t >> 5] = sum;
    __syncthreads();
    float tot = 0.f;
    #pragma unroll
    for (int i = 0; i < 8; i++) tot += red[i];
    float inv = 1.0f / tot;

    float4* o4 = (float4*)p;
    for (int i = t; i < n4; i += 256) {
        float4 v = b4[i];
        v.x *= inv; v.y *= inv; v.z *= inv; v.w *= inv;
        o4[i] = v;
    }
    for (int i = (n4 << 2) + t; i < len; i += 256) p[i] = buf[i] * inv;
}

// ---------------- PV: 128x64 tiles, epilogue emits split bf16 ---------------
__global__ void __launch_bounds__(256) pv_kernel(const float* __restrict__ probs) {
    int bh = blockIdx.y;
    int mt = (int)gridDim.x - 1 - (int)blockIdx.x;
    int b = bh >> 4, h = bh & 15;
    int m0 = mt * 128;

    __shared__ float Ps[32][132];
    __shared__ float Vs[32][68];
    int tid = threadIdx.x;
    int tx = tid & 15, ty = tid >> 4;

    int prow = tid >> 1;
    int pk   = (tid & 1) * 16;
    int vk = tid >> 3;
    int vc = (tid & 7) * 8;

    const float* Prow = probs + ((size_t)bh * SEQ + m0 + prow) * SEQ;
    const float* Vbase = g_qkv + (size_t)(b * SEQ) * QKVDIM + 2 * HIDDEN + h * HEADD;

    float acc[8][4] = {};
    int ktmax = (mt + 1) * 4;
    for (int kt = 0; kt < ktmax; kt++) {
        int k0 = kt * 32;
        #pragma unroll
        for (int q4 = 0; q4 < 4; q4++) {
            float4 v = *(const float4*)(Prow + k0 + pk + q4 * 4);
            Ps[pk + q4 * 4 + 0][prow] = v.x;
            Ps[pk + q4 * 4 + 1][prow] = v.y;
            Ps[pk + q4 * 4 + 2][prow] = v.z;
            Ps[pk + q4 * 4 + 3][prow] = v.w;
        }
        {
            const float* vr = Vbase + (size_t)(k0 + vk) * QKVDIM + vc;
            *(float4*)&Vs[vk][vc]     = *(const float4*)(vr);
            *(float4*)&Vs[vk][vc + 4] = *(const float4*)(vr + 4);
        }
        __syncthreads();
        #pragma unroll
        for (int kk = 0; kk < 32; kk++) {
            float4 a0 = *(const float4*)&Ps[kk][ty * 4];
            float4 a1 = *(const float4*)&Ps[kk][ty * 4 + 64];
            float4 bb = *(const float4*)&Vs[kk][tx * 4];
            float av[8] = {a0.x,a0.y,a0.z,a0.w,a1.x,a1.y,a1.z,a1.w};
            float bv[4] = {bb.x,bb.y,bb.z,bb.w};
            #pragma unroll
            for (int i = 0; i < 8; i++)
                #pragma unroll
                for (int j = 0; j < 4; j++)
                    acc[i][j] += av[i] * bv[j];
        }
        __syncthreads();
    }

    #pragma unroll
    for (int ih = 0; ih < 2; ih++)
        #pragma unroll
        for (int i = 0; i < 4; i++) {
            int rm = m0 + ty * 4 + ih * 64 + i;
            __nv_bfloat16* rowb = g_attn2 + (size_t)(b * SEQ + rm) * KSPLIT;
            store_split4(rowb, h * HEADD + tx * 4,
                         acc[ih*4+i][0], acc[ih*4+i][1], acc[ih*4+i][2], acc[ih*4+i][3]);
        }
}

// ---------------------------------------------------------------------------
extern "C" void kernel_launch(void* const* d_in, const int* in_sizes, int n_in,
                              void* d_out, int out_size) {
    const float* hs    = (const float*)d_in[0];
    const float* Wqkv  = (const float*)d_in[1];
    const float* Wout  = (const float*)d_in[2];
    const float* gamma = (const float*)d_in[3];
    const float* beta  = (const float*)d_in[4];

    float* out = (float*)d_out;
    const size_t OUT_ELEMS   = (size_t)MROWS * HIDDEN;
    const size_t PROBS_ELEMS = (size_t)BATCH * NHEADS * SEQ * SEQ;

    float* probs;
    if ((size_t)out_size >= OUT_ELEMS + PROBS_ELEMS) {
        probs = out + OUT_ELEMS;
    } else {
        void* p; cudaGetSymbolAddress(&p, g_probs_fb);
        probs = (float*)p;
    }

    void* pq;  cudaGetSymbolAddress(&pq, g_qkv);
    void* pa2; cudaGetSymbolAddress(&pa2, g_a2);
    void* pw1; cudaGetSymbolAddress(&pw1, g_wqkv2);
    void* pw2; cudaGetSymbolAddress(&pw2, g_wout2);
    void* pat; cudaGetSymbolAddress(&pat, g_attn2);
    float* qkv = (float*)pq;
    __nv_bfloat16* a2  = (__nv_bfloat16*)pa2;
    __nv_bfloat16* w1  = (__nv_bfloat16*)pw1;
    __nv_bfloat16* w2  = (__nv_bfloat16*)pw2;
    __nv_bfloat16* at2 = (__nv_bfloat16*)pat;

    // 1. LayerNorm -> split bf16
    ln_kernel<<<MROWS, 256>>>(hs, gamma, beta);

    // 2. weight conversions
    conv_w<<<(QKVDIM * HIDDEN / 4 + 255) / 256, 256>>>(Wqkv, w1, QKVDIM * HIDDEN);
    conv_w<<<(HIDDEN * HIDDEN / 4 + 255) / 256, 256>>>(Wout, w2, HIDDEN * HIDDEN);

    // 3. QKV projection (mma.sync bf16 split): [4096 x 3072] = a2 . w1^T
    gemm_bf16<<<dim3(QKVDIM / 128, MROWS / 128), 256>>>(a2, w1, qkv, QKVDIM);

    // 4. RoPE in place
    rope_kernel<<<(MROWS * NHEADS + 127) / 128, 128>>>();

    // 5. scores
    scores_kernel<<<dim3(SEQ / 128, SEQ / 128, BATCH * NHEADS), 256>>>(probs);

    // 6. softmax
    softmax_kernel<<<dim3(SEQ, BATCH * NHEADS), 256>>>(probs);

    // 7. probs @ V -> split bf16
    pv_kernel<<<dim3(SEQ / 128, BATCH * NHEADS), 256>>>(probs);

    // 8. output projection (mma.sync bf16 split)
    gemm_bf16<<<dim3(HIDDEN / 128, MROWS / 128), 256>>>(at2, w2, out, HIDDEN);
}

// round 5
// speedup vs baseline: 2.2504x; 1.1719x over previous
#include <cuda_runtime.h>
#include <cuda_bf16.h>
#include <cstdint>
#include <math.h>

#define BATCH   2
#define SEQ     2048
#define HIDDEN  1024
#define NHEADS  16
#define HEADD   64
#define MROWS   (BATCH*SEQ)      // 4096
#define QKVDIM  (3*HIDDEN)       // 3072
#define KSPLIT  3072             // K' for dense GEMMs
#define KQK     192              // K' for scores (3*64)
#define ATT_SCALE 0.125f
#define LNEPS   1e-5f

// ---------------- scratch (static device memory) ---------------------------
__device__ __nv_bfloat16 g_a2[(size_t)MROWS * KSPLIT];     // LN out split
__device__ __nv_bfloat16 g_wqkv2[(size_t)QKVDIM * KSPLIT];
__device__ __nv_bfloat16 g_wout2[(size_t)HIDDEN * KSPLIT];
__device__ __nv_bfloat16 g_attn2[(size_t)MROWS * KSPLIT];  // attn split
__device__ float g_qkv[(size_t)MROWS * QKVDIM];            // qkv fp32 (V + rope input)
__device__ __nv_bfloat16 g_q2[(size_t)BATCH * NHEADS * SEQ * KQK]; // 25 MB
__device__ __nv_bfloat16 g_k2[(size_t)BATCH * NHEADS * SEQ * KQK]; // 25 MB
__device__ float g_probs_fb[(size_t)BATCH * NHEADS * SEQ * SEQ];

__device__ __forceinline__ uint32_t smem_u32(const void* p) {
    uint32_t a;
    asm("{ .reg .u64 t; cvta.to.shared.u64 t, %1; cvt.u32.u64 %0, t; }" : "=r"(a) : "l"(p));
    return a;
}

// ---------------- bf16 split helpers ----------------------------------------
__device__ __forceinline__ unsigned short bfb(float v) {
    __nv_bfloat16 h = __float2bfloat16(v);
    return *(unsigned short*)&h;
}
__device__ __forceinline__ float bf2f(unsigned short u) {
    __nv_bfloat16 h = *(__nv_bfloat16*)&u;
    return __bfloat162float(h);
}
__device__ __forceinline__ uint32_t pack_hi2(float a, float b) {
    return (uint32_t)bfb(a) | ((uint32_t)bfb(b) << 16);
}
__device__ __forceinline__ uint32_t pack_lo2(float a, float b) {
    unsigned short ha = bfb(a), hb = bfb(b);
    return (uint32_t)bfb(a - bf2f(ha)) | ((uint32_t)bfb(b - bf2f(hb)) << 16);
}
// write 4 consecutive values as (hi,hi,lo) triple-split at row base (stride KSPLIT)
__device__ __forceinline__ void store_split4(__nv_bfloat16* rowbase, int k,
                                             float v0, float v1, float v2, float v3) {
    uint2 hw = { pack_hi2(v0, v1), pack_hi2(v2, v3) };
    uint2 lw = { pack_lo2(v0, v1), pack_lo2(v2, v3) };
    *(uint2*)(rowbase + k)        = hw;
    *(uint2*)(rowbase + 1024 + k) = hw;
    *(uint2*)(rowbase + 2048 + k) = lw;
}

// ---------------- LayerNorm -> split bf16 -----------------------------------
__global__ void ln_kernel(const float* __restrict__ hs,
                          const float* __restrict__ gamma,
                          const float* __restrict__ beta) {
    int row = blockIdx.x;
    int t = threadIdx.x;
    const float4* x4 = (const float4*)(hs + (size_t)row * HIDDEN);
    float4 v = x4[t];
    float s  = v.x + v.y + v.z + v.w;
    float sq = v.x*v.x + v.y*v.y + v.z*v.z + v.w*v.w;
    #pragma unroll
    for (int o = 16; o > 0; o >>= 1) {
        s  += __shfl_xor_sync(0xffffffffu, s,  o);
        sq += __shfl_xor_sync(0xffffffffu, sq, o);
    }
    __shared__ float ss[8], ssq[8];
    if ((t & 31) == 0) { ss[t >> 5] = s; ssq[t >> 5] = sq; }
    __syncthreads();
    float tot = 0.f, totq = 0.f;
    #pragma unroll
    for (int i = 0; i < 8; i++) { tot += ss[i]; totq += ssq[i]; }
    float mean = tot * (1.0f / HIDDEN);
    float var  = totq * (1.0f / HIDDEN) - mean * mean;
    float inv  = rsqrtf(var + LNEPS);

    float4 g = ((const float4*)gamma)[t];
    float4 b = ((const float4*)beta)[t];
    float o0 = (v.x - mean) * inv * g.x + b.x;
    float o1 = (v.y - mean) * inv * g.y + b.y;
    float o2 = (v.z - mean) * inv * g.z + b.z;
    float o3 = (v.w - mean) * inv * g.w + b.w;
    store_split4(g_a2 + (size_t)row * KSPLIT, t * 4, o0, o1, o2, o3);
}

// ---------------- weight conversion: W[N][1024] f32 -> (hi,lo,hi) split -----
__global__ void conv_w(const float* __restrict__ W, __nv_bfloat16* __restrict__ W2, int total) {
    int gid = blockIdx.x * blockDim.x + threadIdx.x;
    int i4 = gid * 4;
    if (i4 >= total) return;
    int n = i4 >> 10, k = i4 & 1023;
    float4 w = *(const float4*)(W + i4);
    uint2 hw = { pack_hi2(w.x, w.y), pack_hi2(w.z, w.w) };
    uint2 lw = { pack_lo2(w.x, w.y), pack_lo2(w.z, w.w) };
    __nv_bfloat16* rb = W2 + (size_t)n * KSPLIT;
    *(uint2*)(rb + k)        = hw;   // hi
    *(uint2*)(rb + 1024 + k) = lw;   // lo
    *(uint2*)(rb + 2048 + k) = hw;   // hi
}

// ---------------- mma helpers ------------------------------------------------
#define SROW   40          // bf16 elems per smem row (80 B)
#define KCHUNK 32
#define STAGES 3
#define STAGEB (128 * SROW * 2)   // bytes per stage per operand (10240)
#define DYNSM  (STAGES * STAGEB * 2)

__device__ __forceinline__ void ldmat4(uint32_t& r0, uint32_t& r1,
                                       uint32_t& r2, uint32_t& r3, uint32_t addr) {
    asm volatile("ldmatrix.sync.aligned.m8n8.x4.shared.b16 {%0,%1,%2,%3}, [%4];"
                 : "=r"(r0), "=r"(r1), "=r"(r2), "=r"(r3) : "r"(addr));
}
__device__ __forceinline__ void mma16816(float* c, const uint32_t* a, uint32_t b0, uint32_t b1) {
    asm volatile("mma.sync.aligned.m16n8k16.row.col.f32.bf16.bf16.f32 "
                 "{%0,%1,%2,%3}, {%4,%5,%6,%7}, {%8,%9}, {%0,%1,%2,%3};"
                 : "+f"(c[0]), "+f"(c[1]), "+f"(c[2]), "+f"(c[3])
                 : "r"(a[0]), "r"(a[1]), "r"(a[2]), "r"(a[3]), "r"(b0), "r"(b1));
}
__device__ __forceinline__ void cpasync16(uint32_t s, const void* g) {
    asm volatile("cp.async.cg.shared.global [%0], [%1], 16;" :: "r"(s), "l"(g));
}
#define CP_COMMIT() asm volatile("cp.async.commit_group;" ::: "memory")
#define CP_WAIT1()  asm volatile("cp.async.wait_group 1;" ::: "memory")
#define CP_WAIT0()  asm volatile("cp.async.wait_group 0;" ::: "memory")

// issue one 32-wide K chunk of A and B into stage slot
__device__ __forceinline__ void issue_chunk(uint32_t smA, uint32_t smB, int slot,
                                            const __nv_bfloat16* Ag, const __nv_bfloat16* Bg,
                                            int kc, int rowoff, int segB) {
    uint32_t so = (uint32_t)slot * STAGEB + (uint32_t)rowoff * 80u + (uint32_t)segB;
    const __nv_bfloat16* ga = Ag + (size_t)kc * KCHUNK;
    const __nv_bfloat16* gb = Bg + (size_t)kc * KCHUNK;
    cpasync16(smA + so,      ga);
    cpasync16(smA + so + 16, ga + 8);
    cpasync16(smB + so,      gb);
    cpasync16(smB + so + 16, gb + 8);
    CP_COMMIT();
}

// ---------------- pipelined mma GEMM: C[M,N] = A2 . B2^T, K'=3072 ----------
__global__ void __launch_bounds__(256) gemm_bf16(const __nv_bfloat16* __restrict__ A2,
                                                 const __nv_bfloat16* __restrict__ B2,
                                                 float* __restrict__ C, int ldc) {
    extern __shared__ __align__(16) char dynsm[];
    uint32_t smA = smem_u32(dynsm);
    uint32_t smB = smA + STAGES * STAGEB;

    int tid = threadIdx.x, lane = tid & 31, w = tid >> 5;
    int wm = w >> 1, wn = w & 1;
    int m0 = blockIdx.y * 128, n0 = blockIdx.x * 128;

    int grow = tid >> 1;
    int gseg = (tid & 1) * 16;   // bf16 elems
    const __nv_bfloat16* Ag = A2 + (size_t)(m0 + grow) * KSPLIT + gseg;
    const __nv_bfloat16* Bg = B2 + (size_t)(n0 + grow) * KSPLIT + gseg;
    int segB = (tid & 1) * 32;   // bytes

    float acc[2][8][4] = {};
    uint32_t aB = smA + (uint32_t)(((wm * 32 + (lane & 15)) * SROW + (lane >> 4) * 8) * 2);
    uint32_t bB = smB + (uint32_t)(((wn * 64 + (lane & 15)) * SROW + (lane >> 4) * 8) * 2);

    const int NCH = KSPLIT / KCHUNK;   // 96
    issue_chunk(smA, smB, 0, Ag, Bg, 0, grow, segB);
    issue_chunk(smA, smB, 1, Ag, Bg, 1, grow, segB);

    for (int kc = 0; kc < NCH; kc++) {
        if (kc + 1 < NCH) CP_WAIT1(); else CP_WAIT0();
        __syncthreads();
        if (kc + 2 < NCH)
            issue_chunk(smA, smB, (kc + 2) % STAGES, Ag, Bg, kc + 2, grow, segB);

        uint32_t soff = (uint32_t)(kc % STAGES) * STAGEB;
        #pragma unroll
        for (int ks = 0; ks < 2; ks++) {
            uint32_t koff = soff + ks * 32;
            uint32_t af[2][4];
            ldmat4(af[0][0], af[0][1], af[0][2], af[0][3], aB + koff);
            ldmat4(af[1][0], af[1][1], af[1][2], af[1][3], aB + 16 * SROW * 2 + koff);
            uint32_t bf_[4][4];
            #pragma unroll
            for (int n2 = 0; n2 < 4; n2++)
                ldmat4(bf_[n2][0], bf_[n2][1], bf_[n2][2], bf_[n2][3],
                       bB + n2 * 16 * SROW * 2 + koff);
            #pragma unroll
            for (int mi = 0; mi < 2; mi++)
                #pragma unroll
                for (int ni = 0; ni < 8; ni++) {
                    int n2 = ni >> 1, p = ni & 1;
                    mma16816(acc[mi][ni], af[mi], bf_[n2][p], bf_[n2][p + 2]);
                }
        }
    }

    #pragma unroll
    for (int mi = 0; mi < 2; mi++)
        #pragma unroll
        for (int ni = 0; ni < 8; ni++) {
            int row = m0 + wm * 32 + mi * 16 + (lane >> 2);
            int col = n0 + wn * 64 + ni * 8 + (lane & 3) * 2;
            float2 w0 = { acc[mi][ni][0], acc[mi][ni][1] };
            float2 w1 = { acc[mi][ni][2], acc[mi][ni][3] };
            *(float2*)(C + (size_t)row * ldc + col)       = w0;
            *(float2*)(C + (size_t)(row + 8) * ldc + col) = w1;
        }
}

// ---------------- RoPE -> split bf16 Q2/K2 ----------------------------------
// grid (SEQ/64, BATCH*NHEADS), block 128. Q2 row: [hi|hi|lo]; K2 row: [hi|lo|hi]
__global__ void __launch_bounds__(128) rope_kernel() {
    __shared__ uint32_t sm[64][97];
    int bh = blockIdx.y;
    int b = bh >> 4, h = bh & 15;
    int s0 = blockIdx.x * 64;
    int t = threadIdx.x;

    float rq[64], rk[64];
    if (t < 64) {
        int s = s0 + t;
        const float* qp = g_qkv + (size_t)(b * SEQ + s) * QKVDIM + h * HEADD;
        const float* kp = qp + HIDDEN;
        float c[32], sn[32];
        const float LOG_TH = 9.210340371976184f;
        #pragma unroll
        for (int j = 0; j < 32; j++) {
            float freq = __expf(-(float)j * (LOG_TH / 32.0f));
            sincosf((float)s * freq, &sn[j], &c[j]);
        }
        float oq[64], ok[64];
        #pragma unroll
        for (int i = 0; i < 64; i++) { oq[i] = qp[i]; ok[i] = kp[i]; }
        #pragma unroll
        for (int j = 0; j < 32; j++) {
            rq[2*j]   = oq[2*j]   * c[j] - oq[32+j] * sn[j];
            rq[2*j+1] = oq[2*j+1] * c[j] + oq[j]    * sn[j];
            rk[2*j]   = ok[2*j]   * c[j] - ok[32+j] * sn[j];
            rk[2*j+1] = ok[2*j+1] * c[j] + ok[j]    * sn[j];
        }
    }

    // ---- stage + write Q2
    if (t < 64) {
        #pragma unroll
        for (int j = 0; j < 32; j++) {
            uint32_t hp = pack_hi2(rq[2*j], rq[2*j+1]);
            sm[t][j]      = hp;
            sm[t][32 + j] = hp;
            sm[t][64 + j] = pack_lo2(rq[2*j], rq[2*j+1]);
        }
    }
    __syncthreads();
    {
        uint32_t* dst = (uint32_t*)(g_q2 + ((size_t)bh * SEQ + s0) * KQK);
        for (int idx = t; idx < 64 * 96; idx += 128) {
            int r = idx / 96, cidx = idx % 96;
            dst[r * 96 + cidx] = sm[r][cidx];
        }
    }
    __syncthreads();

    // ---- stage + write K2 (hi, lo, hi)
    if (t < 64) {
        #pragma unroll
        for (int j = 0; j < 32; j++) {
            uint32_t hp = pack_hi2(rk[2*j], rk[2*j+1]);
            sm[t][j]      = hp;
            sm[t][32 + j] = pack_lo2(rk[2*j], rk[2*j+1]);
            sm[t][64 + j] = hp;
        }
    }
    __syncthreads();
    {
        uint32_t* dst = (uint32_t*)(g_k2 + ((size_t)bh * SEQ + s0) * KQK);
        for (int idx = t; idx < 64 * 96; idx += 128) {
            int r = idx / 96, cidx = idx % 96;
            dst[r * 96 + cidx] = sm[r][cidx];
        }
    }
}

// ---------------- scores via mma: 128x128 tile, K'=192, causal -------------
__global__ void __launch_bounds__(256) scores_kernel(const __nv_bfloat16* __restrict__ Q2,
                                                     const __nv_bfloat16* __restrict__ K2,
                                                     float* __restrict__ probs) {
    int nt = blockIdx.x;
    int mt = 15 - (int)blockIdx.y;
    int bh = blockIdx.z;
    int m0 = mt * 128, n0 = nt * 128;
    int tid = threadIdx.x, lane = tid & 31, w = tid >> 5;
    int wm = w >> 1, wn = w & 1;

    if (nt > mt) {   // fully masked: zero-fill
        int tx = tid & 15, ty = tid >> 4;
        float4 z = {0.f, 0.f, 0.f, 0.f};
        #pragma unroll
        for (int ih = 0; ih < 2; ih++)
            #pragma unroll
            for (int i = 0; i < 4; i++) {
                int rm = m0 + ty * 4 + ih * 64 + i;
                float* row = probs + ((size_t)bh * SEQ + rm) * SEQ + n0;
                *(float4*)(row + tx * 4)      = z;
                *(float4*)(row + tx * 4 + 64) = z;
            }
        return;
    }

    extern __shared__ __align__(16) char dynsm[];
    uint32_t smA = smem_u32(dynsm);
    uint32_t smB = smA + STAGES * STAGEB;

    int grow = tid >> 1;
    int gseg = (tid & 1) * 16;
    const __nv_bfloat16* Ag = Q2 + ((size_t)bh * SEQ + m0 + grow) * KQK + gseg;
    const __nv_bfloat16* Bg = K2 + ((size_t)bh * SEQ + n0 + grow) * KQK + gseg;
    int segB = (tid & 1) * 32;

    float acc[2][8][4] = {};
    uint32_t aB = smA + (uint32_t)(((wm * 32 + (lane & 15)) * SROW + (lane >> 4) * 8) * 2);
    uint32_t bB = smB + (uint32_t)(((wn * 64 + (lane & 15)) * SROW + (lane >> 4) * 8) * 2);

    const int NCH = KQK / KCHUNK;   // 6
    issue_chunk(smA, smB, 0, Ag, Bg, 0, grow, segB);
    issue_chunk(smA, smB, 1, Ag, Bg, 1, grow, segB);

    for (int kc = 0; kc < NCH; kc++) {
        if (kc + 1 < NCH) CP_WAIT1(); else CP_WAIT0();
        __syncthreads();
        if (kc + 2 < NCH)
            issue_chunk(smA, smB, (kc + 2) % STAGES, Ag, Bg, kc + 2, grow, segB);

        uint32_t soff = (uint32_t)(kc % STAGES) * STAGEB;
        #pragma unroll
        for (int ks = 0; ks < 2; ks++) {
            uint32_t koff = soff + ks * 32;
            uint32_t af[2][4];
            ldmat4(af[0][0], af[0][1], af[0][2], af[0][3], aB + koff);
            ldmat4(af[1][0], af[1][1], af[1][2], af[1][3], aB + 16 * SROW * 2 + koff);
            uint32_t bf_[4][4];
            #pragma unroll
            for (int n2 = 0; n2 < 4; n2++)
                ldmat4(bf_[n2][0], bf_[n2][1], bf_[n2][2], bf_[n2][3],
                       bB + n2 * 16 * SROW * 2 + koff);
            #pragma unroll
            for (int mi = 0; mi < 2; mi++)
                #pragma unroll
                for (int ni = 0; ni < 8; ni++) {
                    int n2 = ni >> 1, p = ni & 1;
                    mma16816(acc[mi][ni], af[mi], bf_[n2][p], bf_[n2][p + 2]);
                }
        }
    }

    float* pb = probs + (size_t)bh * SEQ * SEQ;
    if (nt < mt) {
        #pragma unroll
        for (int mi = 0; mi < 2; mi++)
            #pragma unroll
            for (int ni = 0; ni < 8; ni++) {
                int row = m0 + wm * 32 + mi * 16 + (lane >> 2);
                int col = n0 + wn * 64 + ni * 8 + (lane & 3) * 2;
                float2 w0 = { acc[mi][ni][0]*ATT_SCALE, acc[mi][ni][1]*ATT_SCALE };
                float2 w1 = { acc[mi][ni][2]*ATT_SCALE, acc[mi][ni][3]*ATT_SCALE };
                *(float2*)(pb + (size_t)row * SEQ + col)       = w0;
                *(float2*)(pb + (size_t)(row + 8) * SEQ + col) = w1;
            }
    } else {   // diagonal tile
        #pragma unroll
        for (int mi = 0; mi < 2; mi++)
            #pragma unroll
            for (int ni = 0; ni < 8; ni++) {
                int row = m0 + wm * 32 + mi * 16 + (lane >> 2);
                int col = n0 + wn * 64 + ni * 8 + (lane & 3) * 2;
                pb[(size_t)row * SEQ + col]         = (col     <= row)     ? acc[mi][ni][0]*ATT_SCALE : 0.f;
                pb[(size_t)row * SEQ + col + 1]     = (col + 1 <= row)     ? acc[mi][ni][1]*ATT_SCALE : 0.f;
                pb[(size_t)(row+8) * SEQ + col]     = (col     <= row + 8) ? acc[mi][ni][2]*ATT_SCALE : 0.f;
                pb[(size_t)(row+8) * SEQ + col + 1] = (col + 1 <= row + 8) ? acc[mi][ni][3]*ATT_SCALE : 0.f;
            }
    }
}

// ---------------- row softmax ------------------------------------------------
__global__ void softmax_kernel(float* __restrict__ probs) {
    int bh = blockIdx.y;
    int row = blockIdx.x;
    float* p = probs + ((size_t)bh * SEQ + row) * SEQ;
    int len = row + 1;
    int t = threadIdx.x;

    __shared__ float buf[SEQ];
    __shared__ float red[8];

    float mx = -3.4e38f;
    int n4 = len >> 2;
    const float4* p4 = (const float4*)p;
    float4* b4 = (float4*)buf;
    for (int i = t; i < n4; i += 256) {
        float4 v = p4[i]; b4[i] = v;
        mx = fmaxf(mx, fmaxf(fmaxf(v.x, v.y), fmaxf(v.z, v.w)));
    }
    for (int i = (n4 << 2) + t; i < len; i += 256) { float v = p[i]; buf[i] = v; mx = fmaxf(mx, v); }
    #pragma unroll
    for (int o = 16; o > 0; o >>= 1) mx = fmaxf(mx, __shfl_xor_sync(0xffffffffu, mx, o));
    if ((t & 31) == 0) red[t >> 5] = mx;
    __syncthreads();
    mx = red[0];
    #pragma unroll
    for (int i = 1; i < 8; i++) mx = fmaxf(mx, red[i]);
    __syncthreads();

    float sum = 0.f;
    for (int i = t; i < len; i += 256) { float e = __expf(buf[i] - mx); buf[i] = e; sum += e; }
    #pragma unroll
    for (int o = 16; o > 0; o >>= 1) sum += __shfl_xor_sync(0xffffffffu, sum, o);
    if ((t & 31) == 0) red[t >> 5] = sum;
    __syncthreads();
    float tot = 0.f;
    #pragma unroll
    for (int i = 0; i < 8; i++) tot += red[i];
    float inv = 1.0f / tot;

    float4* o4 = (float4*)p;
    for (int i = t; i < n4; i += 256) {
        float4 v = b4[i];
        v.x *= inv; v.y *= inv; v.z *= inv; v.w *= inv;
        o4[i] = v;
    }
    for (int i = (n4 << 2) + t; i < len; i += 256) p[i] = buf[i] * inv;
}

// ---------------- PV: 128x64 tiles, epilogue emits split bf16 ---------------
__global__ void __launch_bounds__(256) pv_kernel(const float* __restrict__ probs) {
    int bh = blockIdx.y;
    int mt = (int)gridDim.x - 1 - (int)blockIdx.x;
    int b = bh >> 4, h = bh & 15;
    int m0 = mt * 128;

    __shared__ float Ps[32][132];
    __shared__ float Vs[32][68];
    int tid = threadIdx.x;
    int tx = tid & 15, ty = tid >> 4;

    int prow = tid >> 1;
    int pk   = (tid & 1) * 16;
    int vk = tid >> 3;
    int vc = (tid & 7) * 8;

    const float* Prow = probs + ((size_t)bh * SEQ + m0 + prow) * SEQ;
    const float* Vbase = g_qkv + (size_t)(b * SEQ) * QKVDIM + 2 * HIDDEN + h * HEADD;

    float acc[8][4] = {};
    int ktmax = (mt + 1) * 4;
    for (int kt = 0; kt < ktmax; kt++) {
        int k0 = kt * 32;
        #pragma unroll
        for (int q4 = 0; q4 < 4; q4++) {
            float4 v = *(const float4*)(Prow + k0 + pk + q4 * 4);
            Ps[pk + q4 * 4 + 0][prow] = v.x;
            Ps[pk + q4 * 4 + 1][prow] = v.y;
            Ps[pk + q4 * 4 + 2][prow] = v.z;
            Ps[pk + q4 * 4 + 3][prow] = v.w;
        }
        {
            const float* vr = Vbase + (size_t)(k0 + vk) * QKVDIM + vc;
            *(float4*)&Vs[vk][vc]     = *(const float4*)(vr);
            *(float4*)&Vs[vk][vc + 4] = *(const float4*)(vr + 4);
        }
        __syncthreads();
        #pragma unroll
        for (int kk = 0; kk < 32; kk++) {
            float4 a0 = *(const float4*)&Ps[kk][ty * 4];
            float4 a1 = *(const float4*)&Ps[kk][ty * 4 + 64];
            float4 bb = *(const float4*)&Vs[kk][tx * 4];
            float av[8] = {a0.x,a0.y,a0.z,a0.w,a1.x,a1.y,a1.z,a1.w};
            float bv[4] = {bb.x,bb.y,bb.z,bb.w};
            #pragma unroll
            for (int i = 0; i < 8; i++)
                #pragma unroll
                for (int j = 0; j < 4; j++)
                    acc[i][j] += av[i] * bv[j];
        }
        __syncthreads();
    }

    #pragma unroll
    for (int ih = 0; ih < 2; ih++)
        #pragma unroll
        for (int i = 0; i < 4; i++) {
            int rm = m0 + ty * 4 + ih * 64 + i;
            __nv_bfloat16* rowb = g_attn2 + (size_t)(b * SEQ + rm) * KSPLIT;
            store_split4(rowb, h * HEADD + tx * 4,
                         acc[ih*4+i][0], acc[ih*4+i][1], acc[ih*4+i][2], acc[ih*4+i][3]);
        }
}

// ---------------------------------------------------------------------------
extern "C" void kernel_launch(void* const* d_in, const int* in_sizes, int n_in,
                              void* d_out, int out_size) {
    const float* hs    = (const float*)d_in[0];
    const float* Wqkv  = (const float*)d_in[1];
    const float* Wout  = (const float*)d_in[2];
    const float* gamma = (const float*)d_in[3];
    const float* beta  = (const float*)d_in[4];

    float* out = (float*)d_out;
    const size_t OUT_ELEMS   = (size_t)MROWS * HIDDEN;
    const size_t PROBS_ELEMS = (size_t)BATCH * NHEADS * SEQ * SEQ;

    float* probs;
    if ((size_t)out_size >= OUT_ELEMS + PROBS_ELEMS) {
        probs = out + OUT_ELEMS;
    } else {
        void* p; cudaGetSymbolAddress(&p, g_probs_fb);
        probs = (float*)p;
    }

    void* pq;  cudaGetSymbolAddress(&pq, g_qkv);
    void* pa2; cudaGetSymbolAddress(&pa2, g_a2);
    void* pw1; cudaGetSymbolAddress(&pw1, g_wqkv2);
    void* pw2; cudaGetSymbolAddress(&pw2, g_wout2);
    void* pat; cudaGetSymbolAddress(&pat, g_attn2);
    void* pq2; cudaGetSymbolAddress(&pq2, g_q2);
    void* pk2; cudaGetSymbolAddress(&pk2, g_k2);
    float* qkv = (float*)pq;
    __nv_bfloat16* a2  = (__nv_bfloat16*)pa2;
    __nv_bfloat16* w1  = (__nv_bfloat16*)pw1;
    __nv_bfloat16* w2  = (__nv_bfloat16*)pw2;
    __nv_bfloat16* at2 = (__nv_bfloat16*)pat;
    __nv_bfloat16* q2  = (__nv_bfloat16*)pq2;
    __nv_bfloat16* k2  = (__nv_bfloat16*)pk2;

    static int smem_set = 0;
    if (!smem_set) {
        cudaFuncSetAttribute(gemm_bf16, cudaFuncAttributeMaxDynamicSharedMemorySize, DYNSM);
        cudaFuncSetAttribute(scores_kernel, cudaFuncAttributeMaxDynamicSharedMemorySize, DYNSM);
        smem_set = 1;
    }

    // 1. LayerNorm -> split bf16
    ln_kernel<<<MROWS, 256>>>(hs, gamma, beta);

    // 2. weight conversions
    conv_w<<<(QKVDIM * HIDDEN / 4 + 255) / 256, 256>>>(Wqkv, w1, QKVDIM * HIDDEN);
    conv_w<<<(HIDDEN * HIDDEN / 4 + 255) / 256, 256>>>(Wout, w2, HIDDEN * HIDDEN);

    // 3. QKV projection (pipelined mma)
    gemm_bf16<<<dim3(QKVDIM / 128, MROWS / 128), 256, DYNSM>>>(a2, w1, qkv, QKVDIM);

    // 4. RoPE -> split Q2/K2
    rope_kernel<<<dim3(SEQ / 64, BATCH * NHEADS), 128>>>();

    // 5. scores (mma, causal)
    scores_kernel<<<dim3(SEQ / 128, SEQ / 128, BATCH * NHEADS), 256, DYNSM>>>(q2, k2, probs);

    // 6. softmax
    softmax_kernel<<<dim3(SEQ, BATCH * NHEADS), 256>>>(probs);

    // 7. probs @ V -> split bf16
    pv_kernel<<<dim3(SEQ / 128, BATCH * NHEADS), 256>>>(probs);

    // 8. output projection (pipelined mma)
    gemm_bf16<<<dim3(HIDDEN / 128, MROWS / 128), 256, DYNSM>>>(at2, w2, out, HIDDEN);
}

// round 6
// speedup vs baseline: 2.4800x; 1.1020x over previous
#include <cuda_runtime.h>
#include <cuda_bf16.h>
#include <cstdint>
#include <math.h>

#define BATCH   2
#define SEQ     2048
#define HIDDEN  1024
#define NHEADS  16
#define HEADD   64
#define MROWS   (BATCH*SEQ)      // 4096
#define QKVDIM  (3*HIDDEN)       // 3072
#define KSPLIT  3072             // K' for dense GEMMs
#define KQK     192              // K' for scores (3*64)
#define ATT_SCALE 0.125f
#define LNEPS   1e-5f

// ---------------- scratch (static device memory) ---------------------------
__device__ __nv_bfloat16 g_a2[(size_t)MROWS * KSPLIT];
__device__ __nv_bfloat16 g_wqkv2[(size_t)QKVDIM * KSPLIT];
__device__ __nv_bfloat16 g_wout2[(size_t)HIDDEN * KSPLIT];
__device__ __nv_bfloat16 g_attn2[(size_t)MROWS * KSPLIT];
__device__ float g_qkv[(size_t)MROWS * QKVDIM];
__device__ __nv_bfloat16 g_q2[(size_t)BATCH * NHEADS * SEQ * KQK];
__device__ __nv_bfloat16 g_k2[(size_t)BATCH * NHEADS * SEQ * KQK];
__device__ float g_probs_fb[(size_t)BATCH * NHEADS * SEQ * SEQ];

__device__ __forceinline__ uint32_t smem_u32(const void* p) {
    uint32_t a;
    asm("{ .reg .u64 t; cvta.to.shared.u64 t, %1; cvt.u32.u64 %0, t; }" : "=r"(a) : "l"(p));
    return a;
}

// ---------------- bf16 split helpers ----------------------------------------
__device__ __forceinline__ unsigned short bfb(float v) {
    __nv_bfloat16 h = __float2bfloat16(v);
    return *(unsigned short*)&h;
}
__device__ __forceinline__ float bf2f(unsigned short u) {
    __nv_bfloat16 h = *(__nv_bfloat16*)&u;
    return __bfloat162float(h);
}
__device__ __forceinline__ uint32_t pack_hi2(float a, float b) {
    return (uint32_t)bfb(a) | ((uint32_t)bfb(b) << 16);
}
__device__ __forceinline__ uint32_t pack_lo2(float a, float b) {
    unsigned short ha = bfb(a), hb = bfb(b);
    return (uint32_t)bfb(a - bf2f(ha)) | ((uint32_t)bfb(b - bf2f(hb)) << 16);
}
__device__ __forceinline__ void store_split4(__nv_bfloat16* rowbase, int k,
                                             float v0, float v1, float v2, float v3) {
    uint2 hw = { pack_hi2(v0, v1), pack_hi2(v2, v3) };
    uint2 lw = { pack_lo2(v0, v1), pack_lo2(v2, v3) };
    *(uint2*)(rowbase + k)        = hw;
    *(uint2*)(rowbase + 1024 + k) = hw;
    *(uint2*)(rowbase + 2048 + k) = lw;
}
__device__ __forceinline__ void store_split2(__nv_bfloat16* rowbase, int k, float a, float b) {
    uint32_t hw = pack_hi2(a, b), lw = pack_lo2(a, b);
    *(uint32_t*)(rowbase + k)        = hw;
    *(uint32_t*)(rowbase + 1024 + k) = hw;
    *(uint32_t*)(rowbase + 2048 + k) = lw;
}

// ---------------- LayerNorm -> split bf16 -----------------------------------
__global__ void ln_kernel(const float* __restrict__ hs,
                          const float* __restrict__ gamma,
                          const float* __restrict__ beta) {
    int row = blockIdx.x;
    int t = threadIdx.x;
    const float4* x4 = (const float4*)(hs + (size_t)row * HIDDEN);
    float4 v = x4[t];
    float s  = v.x + v.y + v.z + v.w;
    float sq = v.x*v.x + v.y*v.y + v.z*v.z + v.w*v.w;
    #pragma unroll
    for (int o = 16; o > 0; o >>= 1) {
        s  += __shfl_xor_sync(0xffffffffu, s,  o);
        sq += __shfl_xor_sync(0xffffffffu, sq, o);
    }
    __shared__ float ss[8], ssq[8];
    if ((t & 31) == 0) { ss[t >> 5] = s; ssq[t >> 5] = sq; }
    __syncthreads();
    float tot = 0.f, totq = 0.f;
    #pragma unroll
    for (int i = 0; i < 8; i++) { tot += ss[i]; totq += ssq[i]; }
    float mean = tot * (1.0f / HIDDEN);
    float var  = totq * (1.0f / HIDDEN) - mean * mean;
    float inv  = rsqrtf(var + LNEPS);

    float4 g = ((const float4*)gamma)[t];
    float4 b = ((const float4*)beta)[t];
    float o0 = (v.x - mean) * inv * g.x + b.x;
    float o1 = (v.y - mean) * inv * g.y + b.y;
    float o2 = (v.z - mean) * inv * g.z + b.z;
    float o3 = (v.w - mean) * inv * g.w + b.w;
    store_split4(g_a2 + (size_t)row * KSPLIT, t * 4, o0, o1, o2, o3);
}

// ---------------- weight conversion -----------------------------------------
__global__ void conv_w(const float* __restrict__ W, __nv_bfloat16* __restrict__ W2, int total) {
    int gid = blockIdx.x * blockDim.x + threadIdx.x;
    int i4 = gid * 4;
    if (i4 >= total) return;
    int n = i4 >> 10, k = i4 & 1023;
    float4 w = *(const float4*)(W + i4);
    uint2 hw = { pack_hi2(w.x, w.y), pack_hi2(w.z, w.w) };
    uint2 lw = { pack_lo2(w.x, w.y), pack_lo2(w.z, w.w) };
    __nv_bfloat16* rb = W2 + (size_t)n * KSPLIT;
    *(uint2*)(rb + k)        = hw;
    *(uint2*)(rb + 1024 + k) = lw;
    *(uint2*)(rb + 2048 + k) = hw;
}

// ---------------- mma plumbing ----------------------------------------------
#define SROWB   144        // bytes per smem row (64 bf16 + 8 pad)
#define KCHUNK  64
#define OPB     (128 * SROWB)     // 18432 bytes, one operand one stage
#define STAGEB2 (2 * OPB)         // 36864
#define DYNSM   (2 * STAGEB2)     // 73728 (2 stages)

__device__ __forceinline__ void ldmat4(uint32_t& r0, uint32_t& r1,
                                       uint32_t& r2, uint32_t& r3, uint32_t addr) {
    asm volatile("ldmatrix.sync.aligned.m8n8.x4.shared.b16 {%0,%1,%2,%3}, [%4];"
                 : "=r"(r0), "=r"(r1), "=r"(r2), "=r"(r3) : "r"(addr));
}
__device__ __forceinline__ void ldmat4t(uint32_t& r0, uint32_t& r1,
                                        uint32_t& r2, uint32_t& r3, uint32_t addr) {
    asm volatile("ldmatrix.sync.aligned.m8n8.x4.trans.shared.b16 {%0,%1,%2,%3}, [%4];"
                 : "=r"(r0), "=r"(r1), "=r"(r2), "=r"(r3) : "r"(addr));
}
__device__ __forceinline__ void mma16816(float* c, const uint32_t* a, uint32_t b0, uint32_t b1) {
    asm volatile("mma.sync.aligned.m16n8k16.row.col.f32.bf16.bf16.f32 "
                 "{%0,%1,%2,%3}, {%4,%5,%6,%7}, {%8,%9}, {%0,%1,%2,%3};"
                 : "+f"(c[0]), "+f"(c[1]), "+f"(c[2]), "+f"(c[3])
                 : "r"(a[0]), "r"(a[1]), "r"(a[2]), "r"(a[3]), "r"(b0), "r"(b1));
}
__device__ __forceinline__ void cpasync16(uint32_t s, const void* g) {
    asm volatile("cp.async.cg.shared.global [%0], [%1], 16;" :: "r"(s), "l"(g));
}
#define CP_COMMIT() asm volatile("cp.async.commit_group;" ::: "memory")
#define CP_WAIT1()  asm volatile("cp.async.wait_group 1;" ::: "memory")
#define CP_WAIT0()  asm volatile("cp.async.wait_group 0;" ::: "memory")

__device__ __forceinline__ void issue64(uint32_t smb, int slot,
                                        const __nv_bfloat16* pa, const __nv_bfloat16* pb,
                                        int row, int half) {
    uint32_t so = smb + (uint32_t)slot * STAGEB2 + (uint32_t)(row * SROWB + half * 64);
    cpasync16(so,      pa);      cpasync16(so + 16, pa + 8);
    cpasync16(so + 32, pa + 16); cpasync16(so + 48, pa + 24);
    uint32_t sb = so + OPB;
    cpasync16(sb,      pb);      cpasync16(sb + 16, pb + 8);
    cpasync16(sb + 32, pb + 16); cpasync16(sb + 48, pb + 24);
    CP_COMMIT();
}

// shared 128x128 mainloop. Ath/Bth are per-thread row pointers (+half*32 elems).
__device__ __forceinline__ void mma_tile_loop(uint32_t smb,
        const __nv_bfloat16* Ath, const __nv_bfloat16* Bth,
        int NCH, int tid, float acc[2][8][4]) {
    int lane = tid & 31, w = tid >> 5;
    int wm = w >> 1, wn = w & 1;
    int row = tid >> 1, half = tid & 1;
    uint32_t aoff = (uint32_t)((wm * 32 + (lane & 15)) * SROWB + (lane >> 4) * 16);
    uint32_t boff = (uint32_t)((wn * 64 + (lane & 15)) * SROWB + (lane >> 4) * 16);

    issue64(smb, 0, Ath, Bth, row, half);
    issue64(smb, 1, Ath + KCHUNK, Bth + KCHUNK, row, half);

    for (int kc = 0; kc < NCH; kc++) {
        if (kc + 1 < NCH) CP_WAIT1(); else CP_WAIT0();
        __syncthreads();
        uint32_t sb = smb + (uint32_t)(kc & 1) * STAGEB2;
        uint32_t aB = sb + aoff;
        uint32_t bB = sb + OPB + boff;
        #pragma unroll
        for (int ks = 0; ks < 4; ks++) {
            uint32_t koff = ks * 32;
            uint32_t af[2][4];
            ldmat4(af[0][0], af[0][1], af[0][2], af[0][3], aB + koff);
            ldmat4(af[1][0], af[1][1], af[1][2], af[1][3], aB + 16 * SROWB + koff);
            uint32_t bf_[4][4];
            #pragma unroll
            for (int n2 = 0; n2 < 4; n2++)
                ldmat4(bf_[n2][0], bf_[n2][1], bf_[n2][2], bf_[n2][3],
                       bB + n2 * 16 * SROWB + koff);
            #pragma unroll
            for (int mi = 0; mi < 2; mi++)
                #pragma unroll
                for (int ni = 0; ni < 8; ni++) {
                    int n2 = ni >> 1, p = ni & 1;
                    mma16816(acc[mi][ni], af[mi], bf_[n2][p], bf_[n2][p + 2]);
                }
        }
        __syncthreads();
        if (kc + 2 < NCH)
            issue64(smb, kc & 1, Ath + (size_t)(kc + 2) * KCHUNK,
                    Bth + (size_t)(kc + 2) * KCHUNK, row, half);
    }
}

// ---------------- dense GEMM -------------------------------------------------
__global__ void __launch_bounds__(256, 2) gemm_bf16(const __nv_bfloat16* __restrict__ A2,
                                                    const __nv_bfloat16* __restrict__ B2,
                                                    float* __restrict__ C, int ldc) {
    extern __shared__ __align__(16) char dynsm[];
    uint32_t smb = smem_u32(dynsm);
    int tid = threadIdx.x, lane = tid & 31, w = tid >> 5;
    int wm = w >> 1, wn = w & 1;
    int m0 = blockIdx.y * 128, n0 = blockIdx.x * 128;
    int row = tid >> 1, half = tid & 1;

    const __nv_bfloat16* Ath = A2 + (size_t)(m0 + row) * KSPLIT + half * 32;
    const __nv_bfloat16* Bth = B2 + (size_t)(n0 + row) * KSPLIT + half * 32;

    float acc[2][8][4] = {};
    mma_tile_loop(smb, Ath, Bth, KSPLIT / KCHUNK, tid, acc);

    #pragma unroll
    for (int mi = 0; mi < 2; mi++)
        #pragma unroll
        for (int ni = 0; ni < 8; ni++) {
            int r = m0 + wm * 32 + mi * 16 + (lane >> 2);
            int c = n0 + wn * 64 + ni * 8 + (lane & 3) * 2;
            float2 w0 = { acc[mi][ni][0], acc[mi][ni][1] };
            float2 w1 = { acc[mi][ni][2], acc[mi][ni][3] };
            *(float2*)(C + (size_t)r * ldc + c)       = w0;
            *(float2*)(C + (size_t)(r + 8) * ldc + c) = w1;
        }
}

// ---------------- RoPE -> split bf16 Q2/K2 ----------------------------------
__global__ void __launch_bounds__(128) rope_kernel() {
    __shared__ uint32_t sm[64][97];
    int bh = blockIdx.y;
    int b = bh >> 4, h = bh & 15;
    int s0 = blockIdx.x * 64;
    int t = threadIdx.x;

    float rq[64], rk[64];
    if (t < 64) {
        int s = s0 + t;
        const float* qp = g_qkv + (size_t)(b * SEQ + s) * QKVDIM + h * HEADD;
        const float* kp = qp + HIDDEN;
        float c[32], sn[32];
        const float LOG_TH = 9.210340371976184f;
        #pragma unroll
        for (int j = 0; j < 32; j++) {
            float freq = __expf(-(float)j * (LOG_TH / 32.0f));
            sincosf((float)s * freq, &sn[j], &c[j]);
        }
        float oq[64], ok[64];
        #pragma unroll
        for (int i = 0; i < 64; i++) { oq[i] = qp[i]; ok[i] = kp[i]; }
        #pragma unroll
        for (int j = 0; j < 32; j++) {
            rq[2*j]   = oq[2*j]   * c[j] - oq[32+j] * sn[j];
            rq[2*j+1] = oq[2*j+1] * c[j] + oq[j]    * sn[j];
            rk[2*j]   = ok[2*j]   * c[j] - ok[32+j] * sn[j];
            rk[2*j+1] = ok[2*j+1] * c[j] + ok[j]    * sn[j];
        }
    }

    if (t < 64) {
        #pragma unroll
        for (int j = 0; j < 32; j++) {
            uint32_t hp = pack_hi2(rq[2*j], rq[2*j+1]);
            sm[t][j]      = hp;
            sm[t][32 + j] = hp;
            sm[t][64 + j] = pack_lo2(rq[2*j], rq[2*j+1]);
        }
    }
    __syncthreads();
    {
        uint32_t* dst = (uint32_t*)(g_q2 + ((size_t)bh * SEQ + s0) * KQK);
        for (int idx = t; idx < 64 * 96; idx += 128) {
            int r = idx / 96, cidx = idx % 96;
            dst[r * 96 + cidx] = sm[r][cidx];
        }
    }
    __syncthreads();

    if (t < 64) {
        #pragma unroll
        for (int j = 0; j < 32; j++) {
            uint32_t hp = pack_hi2(rk[2*j], rk[2*j+1]);
            sm[t][j]      = hp;
            sm[t][32 + j] = pack_lo2(rk[2*j], rk[2*j+1]);
            sm[t][64 + j] = hp;
        }
    }
    __syncthreads();
    {
        uint32_t* dst = (uint32_t*)(g_k2 + ((size_t)bh * SEQ + s0) * KQK);
        for (int idx = t; idx < 64 * 96; idx += 128) {
            int r = idx / 96, cidx = idx % 96;
            dst[r * 96 + cidx] = sm[r][cidx];
        }
    }
}

// ---------------- scores (mma, causal) --------------------------------------
__global__ void __launch_bounds__(256, 2) scores_kernel(const __nv_bfloat16* __restrict__ Q2,
                                                        const __nv_bfloat16* __restrict__ K2,
                                                        float* __restrict__ probs) {
    int nt = blockIdx.x;
    int mt = 15 - (int)blockIdx.y;
    int bh = blockIdx.z;
    int m0 = mt * 128, n0 = nt * 128;
    int tid = threadIdx.x, lane = tid & 31, w = tid >> 5;
    int wm = w >> 1, wn = w & 1;

    if (nt > mt) {
        int tx = tid & 15, ty = tid >> 4;
        float4 z = {0.f, 0.f, 0.f, 0.f};
        #pragma unroll
        for (int ih = 0; ih < 2; ih++)
            #pragma unroll
            for (int i = 0; i < 4; i++) {
                int rm = m0 + ty * 4 + ih * 64 + i;
                float* rowp = probs + ((size_t)bh * SEQ + rm) * SEQ + n0;
                *(float4*)(rowp + tx * 4)      = z;
                *(float4*)(rowp + tx * 4 + 64) = z;
            }
        return;
    }

    extern __shared__ __align__(16) char dynsm[];
    uint32_t smb = smem_u32(dynsm);
    int row = tid >> 1, half = tid & 1;
    const __nv_bfloat16* Ath = Q2 + ((size_t)bh * SEQ + m0 + row) * KQK + half * 32;
    const __nv_bfloat16* Bth = K2 + ((size_t)bh * SEQ + n0 + row) * KQK + half * 32;

    float acc[2][8][4] = {};
    mma_tile_loop(smb, Ath, Bth, KQK / KCHUNK, tid, acc);

    float* pb = probs + (size_t)bh * SEQ * SEQ;
    if (nt < mt) {
        #pragma unroll
        for (int mi = 0; mi < 2; mi++)
            #pragma unroll
            for (int ni = 0; ni < 8; ni++) {
                int r = m0 + wm * 32 + mi * 16 + (lane >> 2);
                int c = n0 + wn * 64 + ni * 8 + (lane & 3) * 2;
                float2 w0 = { acc[mi][ni][0]*ATT_SCALE, acc[mi][ni][1]*ATT_SCALE };
                float2 w1 = { acc[mi][ni][2]*ATT_SCALE, acc[mi][ni][3]*ATT_SCALE };
                *(float2*)(pb + (size_t)r * SEQ + c)       = w0;
                *(float2*)(pb + (size_t)(r + 8) * SEQ + c) = w1;
            }
    } else {
        #pragma unroll
        for (int mi = 0; mi < 2; mi++)
            #pragma unroll
            for (int ni = 0; ni < 8; ni++) {
                int r = m0 + wm * 32 + mi * 16 + (lane >> 2);
                int c = n0 + wn * 64 + ni * 8 + (lane & 3) * 2;
                pb[(size_t)r * SEQ + c]         = (c     <= r)     ? acc[mi][ni][0]*ATT_SCALE : 0.f;
                pb[(size_t)r * SEQ + c + 1]     = (c + 1 <= r)     ? acc[mi][ni][1]*ATT_SCALE : 0.f;
                pb[(size_t)(r+8) * SEQ + c]     = (c     <= r + 8) ? acc[mi][ni][2]*ATT_SCALE : 0.f;
                pb[(size_t)(r+8) * SEQ + c + 1] = (c + 1 <= r + 8) ? acc[mi][ni][3]*ATT_SCALE : 0.f;
            }
    }
}

// ---------------- row softmax ------------------------------------------------
__global__ void softmax_kernel(float* __restrict__ probs) {
    int bh = blockIdx.y;
    int row = blockIdx.x;
    float* p = probs + ((size_t)bh * SEQ + row) * SEQ;
    int len = row + 1;
    int t = threadIdx.x;

    __shared__ float buf[SEQ];
    __shared__ float red[8];

    float mx = -3.4e38f;
    int n4 = len >> 2;
    const float4* p4 = (const float4*)p;
    float4* b4 = (float4*)buf;
    for (int i = t; i < n4; i += 256) {
        float4 v = p4[i]; b4[i] = v;
        mx = fmaxf(mx, fmaxf(fmaxf(v.x, v.y), fmaxf(v.z, v.w)));
    }
    for (int i = (n4 << 2) + t; i < len; i += 256) { float v = p[i]; buf[i] = v; mx = fmaxf(mx, v); }
    #pragma unroll
    for (int o = 16; o > 0; o >>= 1) mx = fmaxf(mx, __shfl_xor_sync(0xffffffffu, mx, o));
    if ((t & 31) == 0) red[t >> 5] = mx;
    __syncthreads();
    mx = red[0];
    #pragma unroll
    for (int i = 1; i < 8; i++) mx = fmaxf(mx, red[i]);
    __syncthreads();

    float sum = 0.f;
    for (int i = t; i < len; i += 256) { float e = __expf(buf[i] - mx); buf[i] = e; sum += e; }
    #pragma unroll
    for (int o = 16; o > 0; o >>= 1) sum += __shfl_xor_sync(0xffffffffu, sum, o);
    if ((t & 31) == 0) red[t >> 5] = sum;
    __syncthreads();
    float tot = 0.f;
    #pragma unroll
    for (int i = 0; i < 8; i++) tot += red[i];
    float inv = 1.0f / tot;

    float4* o4 = (float4*)p;
    for (int i = t; i < n4; i += 256) {
        float4 v = b4[i];
        v.x *= inv; v.y *= inv; v.z *= inv; v.w *= inv;
        o4[i] = v;
    }
    for (int i = (n4 << 2) + t; i < len; i += 256) p[i] = buf[i] * inv;
}

// ---------------- PV via mma (split bf16, 3-term) ----------------------------
// tile 128(m) x 64(n), 256 threads (8 warps: 4m x 2n, warp 32x32), K chunks of 32.
__global__ void __launch_bounds__(256) pv_kernel(const float* __restrict__ probs) {
    __shared__ __align__(16) __nv_bfloat16 Phi[128 * 40];
    __shared__ __align__(16) __nv_bfloat16 Plo[128 * 40];
    __shared__ __align__(16) __nv_bfloat16 Vhi[32 * 72];
    __shared__ __align__(16) __nv_bfloat16 Vlo[32 * 72];

    int bh = blockIdx.y;
    int mt = (int)gridDim.x - 1 - (int)blockIdx.x;
    int b = bh >> 4, h = bh & 15;
    int m0 = mt * 128;
    int tid = threadIdx.x, lane = tid & 31, w = tid >> 5;
    int wm = w >> 1, wn = w & 1;

    int prow = tid >> 1, pseg = (tid & 1) * 16;
    int vrow = tid >> 3, vseg = (tid & 7) * 8;
    const float* Pg = probs + ((size_t)bh * SEQ + m0 + prow) * SEQ + pseg;
    const float* Vg = g_qkv + (size_t)(b * SEQ + vrow) * QKVDIM + 2 * HIDDEN + h * HEADD + vseg;

    float acc[2][4][4] = {};

    uint32_t phiB = smem_u32(Phi) + (uint32_t)((wm * 32 + (lane & 15)) * 80 + (lane >> 4) * 16);
    uint32_t ploB = smem_u32(Plo) + (uint32_t)((wm * 32 + (lane & 15)) * 80 + (lane >> 4) * 16);
    uint32_t vhiB = smem_u32(Vhi) + (uint32_t)(wn * 64 + (lane & 15) * 144 + (lane >> 4) * 16);
    uint32_t vloB = smem_u32(Vlo) + (uint32_t)(wn * 64 + (lane & 15) * 144 + (lane >> 4) * 16);

    int NCH = (mt + 1) * 4;
    float4 p0 = *(const float4*)(Pg);     float4 p1 = *(const float4*)(Pg + 4);
    float4 p2 = *(const float4*)(Pg + 8); float4 p3 = *(const float4*)(Pg + 12);
    float4 v0 = *(const float4*)(Vg);     float4 v1 = *(const float4*)(Vg + 4);

    for (int kc = 0; kc < NCH; kc++) {
        // convert staged chunk into smem
        {
            float pv[16] = {p0.x,p0.y,p0.z,p0.w, p1.x,p1.y,p1.z,p1.w,
                            p2.x,p2.y,p2.z,p2.w, p3.x,p3.y,p3.z,p3.w};
            uint32_t hw[8], lw[8];
            #pragma unroll
            for (int i = 0; i < 8; i++) {
                hw[i] = pack_hi2(pv[2*i], pv[2*i+1]);
                lw[i] = pack_lo2(pv[2*i], pv[2*i+1]);
            }
            uint32_t off = (uint32_t)(prow * 80 + pseg * 2);
            *(uint4*)((char*)Phi + off)      = make_uint4(hw[0], hw[1], hw[2], hw[3]);
            *(uint4*)((char*)Phi + off + 16) = make_uint4(hw[4], hw[5], hw[6], hw[7]);
            *(uint4*)((char*)Plo + off)      = make_uint4(lw[0], lw[1], lw[2], lw[3]);
            *(uint4*)((char*)Plo + off + 16) = make_uint4(lw[4], lw[5], lw[6], lw[7]);

            float vv[8] = {v0.x,v0.y,v0.z,v0.w, v1.x,v1.y,v1.z,v1.w};
            uint32_t vh[4], vl[4];
            #pragma unroll
            for (int i = 0; i < 4; i++) {
                vh[i] = pack_hi2(vv[2*i], vv[2*i+1]);
                vl[i] = pack_lo2(vv[2*i], vv[2*i+1]);
            }
            uint32_t voff = (uint32_t)(vrow * 144 + vseg * 2);
            *(uint4*)((char*)Vhi + voff) = make_uint4(vh[0], vh[1], vh[2], vh[3]);
            *(uint4*)((char*)Vlo + voff) = make_uint4(vl[0], vl[1], vl[2], vl[3]);
        }
        __syncthreads();
        // prefetch next chunk
        if (kc + 1 < NCH) {
            const float* Pn = Pg + (size_t)(kc + 1) * 32;
            p0 = *(const float4*)(Pn);     p1 = *(const float4*)(Pn + 4);
            p2 = *(const float4*)(Pn + 8); p3 = *(const float4*)(Pn + 12);
            const float* Vn = Vg + (size_t)(kc + 1) * 32 * QKVDIM;
            v0 = *(const float4*)(Vn);     v1 = *(const float4*)(Vn + 4);
        }
        // compute: 2 k16 steps, 3 passes
        #pragma unroll
        for (int ks = 0; ks < 2; ks++) {
            uint32_t pk = ks * 32;
            uint32_t vk = ks * 16 * 144;
            uint32_t ahi[2][4], alo[2][4];
            ldmat4(ahi[0][0], ahi[0][1], ahi[0][2], ahi[0][3], phiB + pk);
            ldmat4(ahi[1][0], ahi[1][1], ahi[1][2], ahi[1][3], phiB + 16 * 80 + pk);
            ldmat4(alo[0][0], alo[0][1], alo[0][2], alo[0][3], ploB + pk);
            ldmat4(alo[1][0], alo[1][1], alo[1][2], alo[1][3], ploB + 16 * 80 + pk);
            uint32_t bh_[2][4], bl_[2][4];   // [n-half 0:cols0-15, 1:cols16-31][regs]
            ldmat4t(bh_[0][0], bh_[0][1], bh_[0][2], bh_[0][3], vhiB + vk);
            ldmat4t(bh_[1][0], bh_[1][1], bh_[1][2], bh_[1][3], vhiB + vk + 32);
            ldmat4t(bl_[0][0], bl_[0][1], bl_[0][2], bl_[0][3], vloB + vk);
            ldmat4t(bl_[1][0], bl_[1][1], bl_[1][2], bl_[1][3], vloB + vk + 32);
            #pragma unroll
            for (int mi = 0; mi < 2; mi++)
                #pragma unroll
                for (int hf = 0; hf < 2; hf++)
                    #pragma unroll
                    for (int oc = 0; oc < 2; oc++) {
                        int oct = hf * 2 + oc;
                        mma16816(acc[mi][oct], ahi[mi], bh_[hf][oc*2], bh_[hf][oc*2+1]); // phi*vhi
                        mma16816(acc[mi][oct], ahi[mi], bl_[hf][oc*2], bl_[hf][oc*2+1]); // phi*vlo
                        mma16816(acc[mi][oct], alo[mi], bh_[hf][oc*2], bh_[hf][oc*2+1]); // plo*vhi
                    }
        }
        __syncthreads();
    }

    // epilogue: emit split bf16 into g_attn2
    #pragma unroll
    for (int mi = 0; mi < 2; mi++)
        #pragma unroll
        for (int oct = 0; oct < 4; oct++) {
            int r = m0 + wm * 32 + mi * 16 + (lane >> 2);
            int c = h * HEADD + wn * 32 + oct * 8 + (lane & 3) * 2;
            __nv_bfloat16* row0 = g_attn2 + (size_t)(b * SEQ + r) * KSPLIT;
            __nv_bfloat16* row1 = g_attn2 + (size_t)(b * SEQ + r + 8) * KSPLIT;
            store_split2(row0, c, acc[mi][oct][0], acc[mi][oct][1]);
            store_split2(row1, c, acc[mi][oct][2], acc[mi][oct][3]);
        }
}

// ---------------------------------------------------------------------------
extern "C" void kernel_launch(void* const* d_in, const int* in_sizes, int n_in,
                              void* d_out, int out_size) {
    const float* hs    = (const float*)d_in[0];
    const float* Wqkv  = (const float*)d_in[1];
    const float* Wout  = (const float*)d_in[2];
    const float* gamma = (const float*)d_in[3];
    const float* beta  = (const float*)d_in[4];

    float* out = (float*)d_out;
    const size_t OUT_ELEMS   = (size_t)MROWS * HIDDEN;
    const size_t PROBS_ELEMS = (size_t)BATCH * NHEADS * SEQ * SEQ;

    float* probs;
    if ((size_t)out_size >= OUT_ELEMS + PROBS_ELEMS) {
        probs = out + OUT_ELEMS;
    } else {
        void* p; cudaGetSymbolAddress(&p, g_probs_fb);
        probs = (float*)p;
    }

    void* pq;  cudaGetSymbolAddress(&pq, g_qkv);
    void* pa2; cudaGetSymbolAddress(&pa2, g_a2);
    void* pw1; cudaGetSymbolAddress(&pw1, g_wqkv2);
    void* pw2; cudaGetSymbolAddress(&pw2, g_wout2);
    void* pat; cudaGetSymbolAddress(&pat, g_attn2);
    void* pq2; cudaGetSymbolAddress(&pq2, g_q2);
    void* pk2; cudaGetSymbolAddress(&pk2, g_k2);
    float* qkv = (float*)pq;
    __nv_bfloat16* a2  = (__nv_bfloat16*)pa2;
    __nv_bfloat16* w1  = (__nv_bfloat16*)pw1;
    __nv_bfloat16* w2  = (__nv_bfloat16*)pw2;
    __nv_bfloat16* at2 = (__nv_bfloat16*)pat;
    __nv_bfloat16* q2  = (__nv_bfloat16*)pq2;
    __nv_bfloat16* k2  = (__nv_bfloat16*)pk2;

    static int smem_set = 0;
    if (!smem_set) {
        cudaFuncSetAttribute(gemm_bf16, cudaFuncAttributeMaxDynamicSharedMemorySize, DYNSM);
        cudaFuncSetAttribute(scores_kernel, cudaFuncAttributeMaxDynamicSharedMemorySize, DYNSM);
        smem_set = 1;
    }

    ln_kernel<<<MROWS, 256>>>(hs, gamma, beta);
    conv_w<<<(QKVDIM * HIDDEN / 4 + 255) / 256, 256>>>(Wqkv, w1, QKVDIM * HIDDEN);
    conv_w<<<(HIDDEN * HIDDEN / 4 + 255) / 256, 256>>>(Wout, w2, HIDDEN * HIDDEN);

    gemm_bf16<<<dim3(QKVDIM / 128, MROWS / 128), 256, DYNSM>>>(a2, w1, qkv, QKVDIM);

    rope_kernel<<<dim3(SEQ / 64, BATCH * NHEADS), 128>>>();

    scores_kernel<<<dim3(SEQ / 128, SEQ / 128, BATCH * NHEADS), 256, DYNSM>>>(q2, k2, probs);

    softmax_kernel<<<dim3(SEQ, BATCH * NHEADS), 256>>>(probs);

    pv_kernel<<<dim3(SEQ / 128, BATCH * NHEADS), 256>>>(probs);

    gemm_bf16<<<dim3(HIDDEN / 128, MROWS / 128), 256, DYNSM>>>(at2, w2, out, HIDDEN);
}

// round 7
// speedup vs baseline: 2.6996x; 1.0885x over previous
#include <cuda_runtime.h>
#include <cuda_bf16.h>
#include <cstdint>
#include <math.h>

#define BATCH   2
#define SEQ     2048
#define HIDDEN  1024
#define NHEADS  16
#define HEADD   64
#define MROWS   (BATCH*SEQ)      // 4096
#define QKVDIM  (3*HIDDEN)       // 3072
#define KSPLIT  3072             // K' for dense GEMMs
#define KQK     192              // K' for scores (3*64)
#define ATT_SCALE 0.125f
#define LNEPS   1e-5f

// ---------------- scratch (static device memory) ---------------------------
__device__ __nv_bfloat16 g_a2[(size_t)MROWS * KSPLIT];
__device__ __nv_bfloat16 g_wqkv2[(size_t)QKVDIM * KSPLIT];
__device__ __nv_bfloat16 g_wout2[(size_t)HIDDEN * KSPLIT];
__device__ __nv_bfloat16 g_attn2[(size_t)MROWS * KSPLIT];
__device__ float g_qkv[(size_t)MROWS * QKVDIM];
__device__ __nv_bfloat16 g_q2[(size_t)BATCH * NHEADS * SEQ * KQK];
__device__ __nv_bfloat16 g_k2[(size_t)BATCH * NHEADS * SEQ * KQK];
__device__ float g_probs_fb[(size_t)BATCH * NHEADS * SEQ * SEQ];

__device__ __forceinline__ uint32_t smem_u32(const void* p) {
    uint32_t a;
    asm("{ .reg .u64 t; cvta.to.shared.u64 t, %1; cvt.u32.u64 %0, t; }" : "=r"(a) : "l"(p));
    return a;
}

// ---------------- bf16 split helpers ----------------------------------------
__device__ __forceinline__ unsigned short bfb(float v) {
    __nv_bfloat16 h = __float2bfloat16(v);
    return *(unsigned short*)&h;
}
__device__ __forceinline__ float bf2f(unsigned short u) {
    __nv_bfloat16 h = *(__nv_bfloat16*)&u;
    return __bfloat162float(h);
}
__device__ __forceinline__ uint32_t pack_hi2(float a, float b) {
    return (uint32_t)bfb(a) | ((uint32_t)bfb(b) << 16);
}
__device__ __forceinline__ uint32_t pack_lo2(float a, float b) {
    unsigned short ha = bfb(a), hb = bfb(b);
    return (uint32_t)bfb(a - bf2f(ha)) | ((uint32_t)bfb(b - bf2f(hb)) << 16);
}
__device__ __forceinline__ void store_split4(__nv_bfloat16* rowbase, int k,
                                             float v0, float v1, float v2, float v3) {
    uint2 hw = { pack_hi2(v0, v1), pack_hi2(v2, v3) };
    uint2 lw = { pack_lo2(v0, v1), pack_lo2(v2, v3) };
    *(uint2*)(rowbase + k)        = hw;
    *(uint2*)(rowbase + 1024 + k) = hw;
    *(uint2*)(rowbase + 2048 + k) = lw;
}
__device__ __forceinline__ void store_split2(__nv_bfloat16* rowbase, int k, float a, float b) {
    uint32_t hw = pack_hi2(a, b), lw = pack_lo2(a, b);
    *(uint32_t*)(rowbase + k)        = hw;
    *(uint32_t*)(rowbase + 1024 + k) = hw;
    *(uint32_t*)(rowbase + 2048 + k) = lw;
}

// ---------------- LayerNorm -> split bf16 -----------------------------------
__global__ void ln_kernel(const float* __restrict__ hs,
                          const float* __restrict__ gamma,
                          const float* __restrict__ beta) {
    int row = blockIdx.x;
    int t = threadIdx.x;
    const float4* x4 = (const float4*)(hs + (size_t)row * HIDDEN);
    float4 v = x4[t];
    float s  = v.x + v.y + v.z + v.w;
    float sq = v.x*v.x + v.y*v.y + v.z*v.z + v.w*v.w;
    #pragma unroll
    for (int o = 16; o > 0; o >>= 1) {
        s  += __shfl_xor_sync(0xffffffffu, s,  o);
        sq += __shfl_xor_sync(0xffffffffu, sq, o);
    }
    __shared__ float ss[8], ssq[8];
    if ((t & 31) == 0) { ss[t >> 5] = s; ssq[t >> 5] = sq; }
    __syncthreads();
    float tot = 0.f, totq = 0.f;
    #pragma unroll
    for (int i = 0; i < 8; i++) { tot += ss[i]; totq += ssq[i]; }
    float mean = tot * (1.0f / HIDDEN);
    float var  = totq * (1.0f / HIDDEN) - mean * mean;
    float inv  = rsqrtf(var + LNEPS);

    float4 g = ((const float4*)gamma)[t];
    float4 b = ((const float4*)beta)[t];
    float o0 = (v.x - mean) * inv * g.x + b.x;
    float o1 = (v.y - mean) * inv * g.y + b.y;
    float o2 = (v.z - mean) * inv * g.z + b.z;
    float o3 = (v.w - mean) * inv * g.w + b.w;
    store_split4(g_a2 + (size_t)row * KSPLIT, t * 4, o0, o1, o2, o3);
}

// ---------------- weight conversion -----------------------------------------
__global__ void conv_w(const float* __restrict__ W, __nv_bfloat16* __restrict__ W2, int total) {
    int gid = blockIdx.x * blockDim.x + threadIdx.x;
    int i4 = gid * 4;
    if (i4 >= total) return;
    int n = i4 >> 10, k = i4 & 1023;
    float4 w = *(const float4*)(W + i4);
    uint2 hw = { pack_hi2(w.x, w.y), pack_hi2(w.z, w.w) };
    uint2 lw = { pack_lo2(w.x, w.y), pack_lo2(w.z, w.w) };
    __nv_bfloat16* rb = W2 + (size_t)n * KSPLIT;
    *(uint2*)(rb + k)        = hw;
    *(uint2*)(rb + 1024 + k) = lw;
    *(uint2*)(rb + 2048 + k) = hw;
}

// ---------------- mma plumbing ----------------------------------------------
#define SROWB   80         // bytes per smem row (32 bf16 + 8 pad)
#define KCHUNK  32
#define STAGES  4
#define OPB     (128 * SROWB)     // 10240
#define STAGEB2 (2 * OPB)         // 20480
#define DYNSM   (STAGES * STAGEB2) // 81920

__device__ __forceinline__ void ldmat4(uint32_t& r0, uint32_t& r1,
                                       uint32_t& r2, uint32_t& r3, uint32_t addr) {
    asm volatile("ldmatrix.sync.aligned.m8n8.x4.shared.b16 {%0,%1,%2,%3}, [%4];"
                 : "=r"(r0), "=r"(r1), "=r"(r2), "=r"(r3) : "r"(addr));
}
__device__ __forceinline__ void ldmat4t(uint32_t& r0, uint32_t& r1,
                                        uint32_t& r2, uint32_t& r3, uint32_t addr) {
    asm volatile("ldmatrix.sync.aligned.m8n8.x4.trans.shared.b16 {%0,%1,%2,%3}, [%4];"
                 : "=r"(r0), "=r"(r1), "=r"(r2), "=r"(r3) : "r"(addr));
}
__device__ __forceinline__ void mma16816(float* c, const uint32_t* a, uint32_t b0, uint32_t b1) {
    asm volatile("mma.sync.aligned.m16n8k16.row.col.f32.bf16.bf16.f32 "
                 "{%0,%1,%2,%3}, {%4,%5,%6,%7}, {%8,%9}, {%0,%1,%2,%3};"
                 : "+f"(c[0]), "+f"(c[1]), "+f"(c[2]), "+f"(c[3])
                 : "r"(a[0]), "r"(a[1]), "r"(a[2]), "r"(a[3]), "r"(b0), "r"(b1));
}
__device__ __forceinline__ void cpasync16(uint32_t s, const void* g) {
    asm volatile("cp.async.cg.shared.global [%0], [%1], 16;" :: "r"(s), "l"(g));
}
#define CP_COMMIT() asm volatile("cp.async.commit_group;" ::: "memory")
#define CP_WAIT2()  asm volatile("cp.async.wait_group 2;" ::: "memory")
#define CP_WAIT1()  asm volatile("cp.async.wait_group 1;" ::: "memory")
#define CP_WAIT0()  asm volatile("cp.async.wait_group 0;" ::: "memory")

// one 32-wide K chunk of A and B into stage slot (per-thread: 32B A + 32B B)
__device__ __forceinline__ void issue32(uint32_t smb, int slot,
                                        const __nv_bfloat16* pa, const __nv_bfloat16* pb,
                                        uint32_t throff) {
    uint32_t so = smb + (uint32_t)slot * STAGEB2 + throff;
    cpasync16(so,      pa); cpasync16(so + 16, pa + 8);
    uint32_t sb = so + OPB;
    cpasync16(sb,      pb); cpasync16(sb + 16, pb + 8);
    CP_COMMIT();
}

// shared 128x128 mainloop. Ath/Bth: per-thread pointers (row=tid>>1, half=tid&1).
__device__ __forceinline__ void mma_tile_loop(uint32_t smb,
        const __nv_bfloat16* Ath, const __nv_bfloat16* Bth,
        int NCH, int tid, float acc[2][8][4]) {
    int lane = tid & 31, w = tid >> 5;
    int wm = w >> 1, wn = w & 1;
    uint32_t throff = (uint32_t)((tid >> 1) * SROWB + (tid & 1) * 32);
    uint32_t aoff = (uint32_t)((wm * 32 + (lane & 15)) * SROWB + (lane >> 4) * 16);
    uint32_t boff = (uint32_t)((wn * 64 + (lane & 15)) * SROWB + (lane >> 4) * 16);

    issue32(smb, 0, Ath,              Bth,              throff);
    issue32(smb, 1, Ath + KCHUNK,     Bth + KCHUNK,     throff);
    issue32(smb, 2, Ath + 2 * KCHUNK, Bth + 2 * KCHUNK, throff);

    for (int kc = 0; kc < NCH; kc++) {
        if (kc + 2 < NCH)      CP_WAIT2();
        else if (kc + 1 < NCH) CP_WAIT1();
        else                   CP_WAIT0();
        __syncthreads();
        // issue 3-ahead into the slot vacated by chunk kc-1 (all warps are
        // provably past its compute thanks to the barrier above)
        if (kc + 3 < NCH)
            issue32(smb, (kc + 3) & 3, Ath + (size_t)(kc + 3) * KCHUNK,
                    Bth + (size_t)(kc + 3) * KCHUNK, throff);

        uint32_t sb = smb + (uint32_t)(kc & 3) * STAGEB2;
        uint32_t aB = sb + aoff;
        uint32_t bB = sb + OPB + boff;
        #pragma unroll
        for (int ks = 0; ks < 2; ks++) {
            uint32_t koff = ks * 32;
            uint32_t af[2][4];
            ldmat4(af[0][0], af[0][1], af[0][2], af[0][3], aB + koff);
            ldmat4(af[1][0], af[1][1], af[1][2], af[1][3], aB + 16 * SROWB + koff);
            uint32_t bf_[4][4];
            #pragma unroll
            for (int n2 = 0; n2 < 4; n2++)
                ldmat4(bf_[n2][0], bf_[n2][1], bf_[n2][2], bf_[n2][3],
                       bB + n2 * 16 * SROWB + koff);
            #pragma unroll
            for (int mi = 0; mi < 2; mi++)
                #pragma unroll
                for (int ni = 0; ni < 8; ni++) {
                    int n2 = ni >> 1, p = ni & 1;
                    mma16816(acc[mi][ni], af[mi], bf_[n2][p], bf_[n2][p + 2]);
                }
        }
    }
}

// ---------------- dense GEMM -------------------------------------------------
__global__ void __launch_bounds__(256, 2) gemm_bf16(const __nv_bfloat16* __restrict__ A2,
                                                    const __nv_bfloat16* __restrict__ B2,
                                                    float* __restrict__ C, int ldc) {
    extern __shared__ __align__(16) char dynsm[];
    uint32_t smb = smem_u32(dynsm);
    int tid = threadIdx.x, lane = tid & 31, w = tid >> 5;
    int wm = w >> 1, wn = w & 1;
    int m0 = blockIdx.y * 128, n0 = blockIdx.x * 128;
    int row = tid >> 1, half = tid & 1;

    const __nv_bfloat16* Ath = A2 + (size_t)(m0 + row) * KSPLIT + half * 16;
    const __nv_bfloat16* Bth = B2 + (size_t)(n0 + row) * KSPLIT + half * 16;

    float acc[2][8][4] = {};
    mma_tile_loop(smb, Ath, Bth, KSPLIT / KCHUNK, tid, acc);

    #pragma unroll
    for (int mi = 0; mi < 2; mi++)
        #pragma unroll
        for (int ni = 0; ni < 8; ni++) {
            int r = m0 + wm * 32 + mi * 16 + (lane >> 2);
            int c = n0 + wn * 64 + ni * 8 + (lane & 3) * 2;
            float2 w0 = { acc[mi][ni][0], acc[mi][ni][1] };
            float2 w1 = { acc[mi][ni][2], acc[mi][ni][3] };
            *(float2*)(C + (size_t)r * ldc + c)       = w0;
            *(float2*)(C + (size_t)(r + 8) * ldc + c) = w1;
        }
}

// ---------------- RoPE -> split bf16 Q2/K2 ----------------------------------
__global__ void __launch_bounds__(128) rope_kernel() {
    __shared__ uint32_t sm[64][97];
    int bh = blockIdx.y;
    int b = bh >> 4, h = bh & 15;
    int s0 = blockIdx.x * 64;
    int t = threadIdx.x;

    float rq[64], rk[64];
    if (t < 64) {
        int s = s0 + t;
        const float* qp = g_qkv + (size_t)(b * SEQ + s) * QKVDIM + h * HEADD;
        const float* kp = qp + HIDDEN;
        float c[32], sn[32];
        const float LOG_TH = 9.210340371976184f;
        #pragma unroll
        for (int j = 0; j < 32; j++) {
            float freq = __expf(-(float)j * (LOG_TH / 32.0f));
            sincosf((float)s * freq, &sn[j], &c[j]);
        }
        float oq[64], ok[64];
        #pragma unroll
        for (int i = 0; i < 64; i++) { oq[i] = qp[i]; ok[i] = kp[i]; }
        #pragma unroll
        for (int j = 0; j < 32; j++) {
            rq[2*j]   = oq[2*j]   * c[j] - oq[32+j] * sn[j];
            rq[2*j+1] = oq[2*j+1] * c[j] + oq[j]    * sn[j];
            rk[2*j]   = ok[2*j]   * c[j] - ok[32+j] * sn[j];
            rk[2*j+1] = ok[2*j+1] * c[j] + ok[j]    * sn[j];
        }
    }

    if (t < 64) {
        #pragma unroll
        for (int j = 0; j < 32; j++) {
            uint32_t hp = pack_hi2(rq[2*j], rq[2*j+1]);
            sm[t][j]      = hp;
            sm[t][32 + j] = hp;
            sm[t][64 + j] = pack_lo2(rq[2*j], rq[2*j+1]);
        }
    }
    __syncthreads();
    {
        uint32_t* dst = (uint32_t*)(g_q2 + ((size_t)bh * SEQ + s0) * KQK);
        for (int idx = t; idx < 64 * 96; idx += 128) {
            int r = idx / 96, cidx = idx % 96;
            dst[r * 96 + cidx] = sm[r][cidx];
        }
    }
    __syncthreads();

    if (t < 64) {
        #pragma unroll
        for (int j = 0; j < 32; j++) {
            uint32_t hp = pack_hi2(rk[2*j], rk[2*j+1]);
            sm[t][j]      = hp;
            sm[t][32 + j] = pack_lo2(rk[2*j], rk[2*j+1]);
            sm[t][64 + j] = hp;
        }
    }
    __syncthreads();
    {
        uint32_t* dst = (uint32_t*)(g_k2 + ((size_t)bh * SEQ + s0) * KQK);
        for (int idx = t; idx < 64 * 96; idx += 128) {
            int r = idx / 96, cidx = idx % 96;
            dst[r * 96 + cidx] = sm[r][cidx];
        }
    }
}

// ---------------- scores (mma, causal) --------------------------------------
__global__ void __launch_bounds__(256, 2) scores_kernel(const __nv_bfloat16* __restrict__ Q2,
                                                        const __nv_bfloat16* __restrict__ K2,
                                                        float* __restrict__ probs) {
    int nt = blockIdx.x;
    int mt = 15 - (int)blockIdx.y;
    int bh = blockIdx.z;
    int m0 = mt * 128, n0 = nt * 128;
    int tid = threadIdx.x, lane = tid & 31, w = tid >> 5;
    int wm = w >> 1, wn = w & 1;

    if (nt > mt) {
        int tx = tid & 15, ty = tid >> 4;
        float4 z = {0.f, 0.f, 0.f, 0.f};
        #pragma unroll
        for (int ih = 0; ih < 2; ih++)
            #pragma unroll
            for (int i = 0; i < 4; i++) {
                int rm = m0 + ty * 4 + ih * 64 + i;
                float* rowp = probs + ((size_t)bh * SEQ + rm) * SEQ + n0;
                *(float4*)(rowp + tx * 4)      = z;
                *(float4*)(rowp + tx * 4 + 64) = z;
            }
        return;
    }

    extern __shared__ __align__(16) char dynsm[];
    uint32_t smb = smem_u32(dynsm);
    int row = tid >> 1, half = tid & 1;
    const __nv_bfloat16* Ath = Q2 + ((size_t)bh * SEQ + m0 + row) * KQK + half * 16;
    const __nv_bfloat16* Bth = K2 + ((size_t)bh * SEQ + n0 + row) * KQK + half * 16;

    float acc[2][8][4] = {};
    mma_tile_loop(smb, Ath, Bth, KQK / KCHUNK, tid, acc);

    float* pb = probs + (size_t)bh * SEQ * SEQ;
    if (nt < mt) {
        #pragma unroll
        for (int mi = 0; mi < 2; mi++)
            #pragma unroll
            for (int ni = 0; ni < 8; ni++) {
                int r = m0 + wm * 32 + mi * 16 + (lane >> 2);
                int c = n0 + wn * 64 + ni * 8 + (lane & 3) * 2;
                float2 w0 = { acc[mi][ni][0]*ATT_SCALE, acc[mi][ni][1]*ATT_SCALE };
                float2 w1 = { acc[mi][ni][2]*ATT_SCALE, acc[mi][ni][3]*ATT_SCALE };
                *(float2*)(pb + (size_t)r * SEQ + c)       = w0;
                *(float2*)(pb + (size_t)(r + 8) * SEQ + c) = w1;
            }
    } else {
        #pragma unroll
        for (int mi = 0; mi < 2; mi++)
            #pragma unroll
            for (int ni = 0; ni < 8; ni++) {
                int r = m0 + wm * 32 + mi * 16 + (lane >> 2);
                int c = n0 + wn * 64 + ni * 8 + (lane & 3) * 2;
                pb[(size_t)r * SEQ + c]         = (c     <= r)     ? acc[mi][ni][0]*ATT_SCALE : 0.f;
                pb[(size_t)r * SEQ + c + 1]     = (c + 1 <= r)     ? acc[mi][ni][1]*ATT_SCALE : 0.f;
                pb[(size_t)(r+8) * SEQ + c]     = (c     <= r + 8) ? acc[mi][ni][2]*ATT_SCALE : 0.f;
                pb[(size_t)(r+8) * SEQ + c + 1] = (c + 1 <= r + 8) ? acc[mi][ni][3]*ATT_SCALE : 0.f;
            }
    }
}

// ---------------- row softmax ------------------------------------------------
__global__ void softmax_kernel(float* __restrict__ probs) {
    int bh = blockIdx.y;
    int row = blockIdx.x;
    float* p = probs + ((size_t)bh * SEQ + row) * SEQ;
    int len = row + 1;
    int t = threadIdx.x;

    __shared__ float buf[SEQ];
    __shared__ float red[8];

    float mx = -3.4e38f;
    int n4 = len >> 2;
    const float4* p4 = (const float4*)p;
    float4* b4 = (float4*)buf;
    for (int i = t; i < n4; i += 256) {
        float4 v = p4[i]; b4[i] = v;
        mx = fmaxf(mx, fmaxf(fmaxf(v.x, v.y), fmaxf(v.z, v.w)));
    }
    for (int i = (n4 << 2) + t; i < len; i += 256) { float v = p[i]; buf[i] = v; mx = fmaxf(mx, v); }
    #pragma unroll
    for (int o = 16; o > 0; o >>= 1) mx = fmaxf(mx, __shfl_xor_sync(0xffffffffu, mx, o));
    if ((t & 31) == 0) red[t >> 5] = mx;
    __syncthreads();
    mx = red[0];
    #pragma unroll
    for (int i = 1; i < 8; i++) mx = fmaxf(mx, red[i]);
    __syncthreads();

    float sum = 0.f;
    for (int i = t; i < len; i += 256) { float e = __expf(buf[i] - mx); buf[i] = e; sum += e; }
    #pragma unroll
    for (int o = 16; o > 0; o >>= 1) sum += __shfl_xor_sync(0xffffffffu, sum, o);
    if ((t & 31) == 0) red[t >> 5] = sum;
    __syncthreads();
    float tot = 0.f;
    #pragma unroll
    for (int i = 0; i < 8; i++) tot += red[i];
    float inv = 1.0f / tot;

    float4* o4 = (float4*)p;
    for (int i = t; i < n4; i += 256) {
        float4 v = b4[i];
        v.x *= inv; v.y *= inv; v.z *= inv; v.w *= inv;
        o4[i] = v;
    }
    for (int i = (n4 << 2) + t; i < len; i += 256) p[i] = buf[i] * inv;
}

// ---------------- PV via mma (split bf16, 3-term) ----------------------------
__global__ void __launch_bounds__(256) pv_kernel(const float* __restrict__ probs) {
    __shared__ __align__(16) __nv_bfloat16 Phi[128 * 40];
    __shared__ __align__(16) __nv_bfloat16 Plo[128 * 40];
    __shared__ __align__(16) __nv_bfloat16 Vhi[32 * 72];
    __shared__ __align__(16) __nv_bfloat16 Vlo[32 * 72];

    int bh = blockIdx.y;
    int mt = (int)gridDim.x - 1 - (int)blockIdx.x;
    int b = bh >> 4, h = bh & 15;
    int m0 = mt * 128;
    int tid = threadIdx.x, lane = tid & 31, w = tid >> 5;
    int wm = w >> 1, wn = w & 1;

    int prow = tid >> 1, pseg = (tid & 1) * 16;
    int vrow = tid >> 3, vseg = (tid & 7) * 8;
    const float* Pg = probs + ((size_t)bh * SEQ + m0 + prow) * SEQ + pseg;
    const float* Vg = g_qkv + (size_t)(b * SEQ + vrow) * QKVDIM + 2 * HIDDEN + h * HEADD + vseg;

    float acc[2][4][4] = {};

    uint32_t phiB = smem_u32(Phi) + (uint32_t)((wm * 32 + (lane & 15)) * 80 + (lane >> 4) * 16);
    uint32_t ploB = smem_u32(Plo) + (uint32_t)((wm * 32 + (lane & 15)) * 80 + (lane >> 4) * 16);
    uint32_t vhiB = smem_u32(Vhi) + (uint32_t)(wn * 64 + (lane & 15) * 144 + (lane >> 4) * 16);
    uint32_t vloB = smem_u32(Vlo) + (uint32_t)(wn * 64 + (lane & 15) * 144 + (lane >> 4) * 16);

    int NCH = (mt + 1) * 4;
    float4 p0 = *(const float4*)(Pg);     float4 p1 = *(const float4*)(Pg + 4);
    float4 p2 = *(const float4*)(Pg + 8); float4 p3 = *(const float4*)(Pg + 12);
    float4 v0 = *(const float4*)(Vg);     float4 v1 = *(const float4*)(Vg + 4);

    for (int kc = 0; kc < NCH; kc++) {
        {
            float pv[16] = {p0.x,p0.y,p0.z,p0.w, p1.x,p1.y,p1.z,p1.w,
                            p2.x,p2.y,p2.z,p2.w, p3.x,p3.y,p3.z,p3.w};
            uint32_t hw[8], lw[8];
            #pragma unroll
            for (int i = 0; i < 8; i++) {
                hw[i] = pack_hi2(pv[2*i], pv[2*i+1]);
                lw[i] = pack_lo2(pv[2*i], pv[2*i+1]);
            }
            uint32_t off = (uint32_t)(prow * 80 + pseg * 2);
            *(uint4*)((char*)Phi + off)      = make_uint4(hw[0], hw[1], hw[2], hw[3]);
            *(uint4*)((char*)Phi + off + 16) = make_uint4(hw[4], hw[5], hw[6], hw[7]);
            *(uint4*)((char*)Plo + off)      = make_uint4(lw[0], lw[1], lw[2], lw[3]);
            *(uint4*)((char*)Plo + off + 16) = make_uint4(lw[4], lw[5], lw[6], lw[7]);

            float vv[8] = {v0.x,v0.y,v0.z,v0.w, v1.x,v1.y,v1.z,v1.w};
            uint32_t vh[4], vl[4];
            #pragma unroll
            for (int i = 0; i < 4; i++) {
                vh[i] = pack_hi2(vv[2*i], vv[2*i+1]);
                vl[i] = pack_lo2(vv[2*i], vv[2*i+1]);
            }
            uint32_t voff = (uint32_t)(vrow * 144 + vseg * 2);
            *(uint4*)((char*)Vhi + voff) = make_uint4(vh[0], vh[1], vh[2], vh[3]);
            *(uint4*)((char*)Vlo + voff) = make_uint4(vl[0], vl[1], vl[2], vl[3]);
        }
        __syncthreads();
        if (kc + 1 < NCH) {
            const float* Pn = Pg + (size_t)(kc + 1) * 32;
            p0 = *(const float4*)(Pn);     p1 = *(const float4*)(Pn + 4);
            p2 = *(const float4*)(Pn + 8); p3 = *(const float4*)(Pn + 12);
            const float* Vn = Vg + (size_t)(kc + 1) * 32 * QKVDIM;
            v0 = *(const float4*)(Vn);     v1 = *(const float4*)(Vn + 4);
        }
        #pragma unroll
        for (int ks = 0; ks < 2; ks++) {
            uint32_t pk = ks * 32;
            uint32_t vk = ks * 16 * 144;
            uint32_t ahi[2][4], alo[2][4];
            ldmat4(ahi[0][0], ahi[0][1], ahi[0][2], ahi[0][3], phiB + pk);
            ldmat4(ahi[1][0], ahi[1][1], ahi[1][2], ahi[1][3], phiB + 16 * 80 + pk);
            ldmat4(alo[0][0], alo[0][1], alo[0][2], alo[0][3], ploB + pk);
            ldmat4(alo[1][0], alo[1][1], alo[1][2], alo[1][3], ploB + 16 * 80 + pk);
            uint32_t bh_[2][4], bl_[2][4];
            ldmat4t(bh_[0][0], bh_[0][1], bh_[0][2], bh_[0][3], vhiB + vk);
            ldmat4t(bh_[1][0], bh_[1][1], bh_[1][2], bh_[1][3], vhiB + vk + 32);
            ldmat4t(bl_[0][0], bl_[0][1], bl_[0][2], bl_[0][3], vloB + vk);
            ldmat4t(bl_[1][0], bl_[1][1], bl_[1][2], bl_[1][3], vloB + vk + 32);
            #pragma unroll
            for (int mi = 0; mi < 2; mi++)
                #pragma unroll
                for (int hf = 0; hf < 2; hf++)
                    #pragma unroll
                    for (int oc = 0; oc < 2; oc++) {
                        int oct = hf * 2 + oc;
                        mma16816(acc[mi][oct], ahi[mi], bh_[hf][oc*2], bh_[hf][oc*2+1]);
                        mma16816(acc[mi][oct], ahi[mi], bl_[hf][oc*2], bl_[hf][oc*2+1]);
                        mma16816(acc[mi][oct], alo[mi], bh_[hf][oc*2], bh_[hf][oc*2+1]);
                    }
        }
        __syncthreads();
    }

    #pragma unroll
    for (int mi = 0; mi < 2; mi++)
        #pragma unroll
        for (int oct = 0; oct < 4; oct++) {
            int r = m0 + wm * 32 + mi * 16 + (lane >> 2);
            int c = h * HEADD + wn * 32 + oct * 8 + (lane & 3) * 2;
            __nv_bfloat16* row0 = g_attn2 + (size_t)(b * SEQ + r) * KSPLIT;
            __nv_bfloat16* row1 = g_attn2 + (size_t)(b * SEQ + r + 8) * KSPLIT;
            store_split2(row0, c, acc[mi][oct][0], acc[mi][oct][1]);
            store_split2(row1, c, acc[mi][oct][2], acc[mi][oct][3]);
        }
}

// ---------------------------------------------------------------------------
extern "C" void kernel_launch(void* const* d_in, const int* in_sizes, int n_in,
                              void* d_out, int out_size) {
    const float* hs    = (const float*)d_in[0];
    const float* Wqkv  = (const float*)d_in[1];
    const float* Wout  = (const float*)d_in[2];
    const float* gamma = (const float*)d_in[3];
    const float* beta  = (const float*)d_in[4];

    float* out = (float*)d_out;
    const size_t OUT_ELEMS   = (size_t)MROWS * HIDDEN;
    const size_t PROBS_ELEMS = (size_t)BATCH * NHEADS * SEQ * SEQ;

    float* probs;
    if ((size_t)out_size >= OUT_ELEMS + PROBS_ELEMS) {
        probs = out + OUT_ELEMS;
    } else {
        void* p; cudaGetSymbolAddress(&p, g_probs_fb);
        probs = (float*)p;
    }

    void* pq;  cudaGetSymbolAddress(&pq, g_qkv);
    void* pa2; cudaGetSymbolAddress(&pa2, g_a2);
    void* pw1; cudaGetSymbolAddress(&pw1, g_wqkv2);
    void* pw2; cudaGetSymbolAddress(&pw2, g_wout2);
    void* pat; cudaGetSymbolAddress(&pat, g_attn2);
    void* pq2; cudaGetSymbolAddress(&pq2, g_q2);
    void* pk2; cudaGetSymbolAddress(&pk2, g_k2);
    float* qkv = (float*)pq;
    __nv_bfloat16* a2  = (__nv_bfloat16*)pa2;
    __nv_bfloat16* w1  = (__nv_bfloat16*)pw1;
    __nv_bfloat16* w2  = (__nv_bfloat16*)pw2;
    __nv_bfloat16* at2 = (__nv_bfloat16*)pat;
    __nv_bfloat16* q2  = (__nv_bfloat16*)pq2;
    __nv_bfloat16* k2  = (__nv_bfloat16*)pk2;

    static int smem_set = 0;
    if (!smem_set) {
        cudaFuncSetAttribute(gemm_bf16, cudaFuncAttributeMaxDynamicSharedMemorySize, DYNSM);
        cudaFuncSetAttribute(scores_kernel, cudaFuncAttributeMaxDynamicSharedMemorySize, DYNSM);
        smem_set = 1;
    }

    ln_kernel<<<MROWS, 256>>>(hs, gamma, beta);
    conv_w<<<(QKVDIM * HIDDEN / 4 + 255) / 256, 256>>>(Wqkv, w1, QKVDIM * HIDDEN);
    conv_w<<<(HIDDEN * HIDDEN / 4 + 255) / 256, 256>>>(Wout, w2, HIDDEN * HIDDEN);

    gemm_bf16<<<dim3(QKVDIM / 128, MROWS / 128), 256, DYNSM>>>(a2, w1, qkv, QKVDIM);

    rope_kernel<<<dim3(SEQ / 64, BATCH * NHEADS), 128>>>();

    scores_kernel<<<dim3(SEQ / 128, SEQ / 128, BATCH * NHEADS), 256, DYNSM>>>(q2, k2, probs);

    softmax_kernel<<<dim3(SEQ, BATCH * NHEADS), 256>>>(probs);

    pv_kernel<<<dim3(SEQ / 128, BATCH * NHEADS), 256>>>(probs);

    gemm_bf16<<<dim3(HIDDEN / 128, MROWS / 128), 256, DYNSM>>>(at2, w2, out, HIDDEN);
}